// round 5
// baseline (speedup 1.0000x reference)
#include <cuda_runtime.h>
#include <cuda_bf16.h>
#include <math.h>
#include <stdint.h>

#define B_   2
#define T_   2048
#define D_   512
#define H_   8
#define DH_  64
#define M_   (B_*T_)   // 4096 token rows

// Scratch (no cudaMalloc allowed)
__device__ __nv_bfloat16 g_hb[M_*D_];        // LN output, bf16
__device__ __nv_bfloat16 g_wb[4*D_*D_];      // bf16 weights: q,k,v,o
__device__ __nv_bfloat16 g_qb[M_*D_];        // q (pre-scaled by 1/8), bf16
__device__ __nv_bfloat16 g_kb[M_*D_];
__device__ __nv_bfloat16 g_vb[M_*D_];
__device__ __nv_bfloat16 g_ctxb[M_*D_];      // attention output, bf16

__device__ __forceinline__ uint32_t smem_u32(const void* p) {
    return (uint32_t)__cvta_generic_to_shared(p);
}

#define CP_ASYNC16(dst, src) \
    asm volatile("cp.async.cg.shared.global [%0], [%1], 16;" :: "r"(dst), "l"(src))
#define CP_COMMIT() asm volatile("cp.async.commit_group;")
#define CP_WAIT(n)  asm volatile("cp.async.wait_group %0;" :: "n"(n))

// ---------------------------------------------------------------------------
// 1) LayerNorm -> bf16 h
// ---------------------------------------------------------------------------
__global__ __launch_bounds__(256) void ln_kernel(const float* __restrict__ x,
                                                 const float* __restrict__ gamma,
                                                 const float* __restrict__ beta) {
    int row = blockIdx.x;
    int tid = threadIdx.x;
    const float* xr = x + (size_t)row * D_;
    float v0 = xr[tid], v1 = xr[tid + 256];
    float s  = v0 + v1;
    float s2 = v0 * v0 + v1 * v1;
    #pragma unroll
    for (int o = 16; o > 0; o >>= 1) {
        s  += __shfl_xor_sync(0xFFFFFFFFu, s,  o);
        s2 += __shfl_xor_sync(0xFFFFFFFFu, s2, o);
    }
    __shared__ float rs[8], rs2[8];
    int wid = tid >> 5, lane = tid & 31;
    if (lane == 0) { rs[wid] = s; rs2[wid] = s2; }
    __syncthreads();
    if (wid == 0) {
        s  = (lane < 8) ? rs[lane]  : 0.f;
        s2 = (lane < 8) ? rs2[lane] : 0.f;
        #pragma unroll
        for (int o = 4; o > 0; o >>= 1) {
            s  += __shfl_xor_sync(0xFFFFFFFFu, s,  o);
            s2 += __shfl_xor_sync(0xFFFFFFFFu, s2, o);
        }
        if (lane == 0) { rs[0] = s; rs2[0] = s2; }
    }
    __syncthreads();
    float mean = rs[0] * (1.0f / D_);
    float var  = rs2[0] * (1.0f / D_) - mean * mean;
    float rstd = rsqrtf(var + 1e-3f);
    __nv_bfloat16* hr = g_hb + (size_t)row * D_;
    hr[tid]       = __float2bfloat16_rn((v0 - mean) * rstd * gamma[tid]       + beta[tid]);
    hr[tid + 256] = __float2bfloat16_rn((v1 - mean) * rstd * gamma[tid + 256] + beta[tid + 256]);
}

// ---------------------------------------------------------------------------
// 1b) Weight conversion fp32 -> bf16
// ---------------------------------------------------------------------------
__global__ __launch_bounds__(256) void conv_kernel(const float* __restrict__ Wq,
                                                   const float* __restrict__ Wk,
                                                   const float* __restrict__ Wv,
                                                   const float* __restrict__ Wo) {
    size_t idx = ((size_t)blockIdx.x * 256 + threadIdx.x) * 4;
    int m = (int)(idx >> 18);
    size_t off = idx & ((1u << 18) - 1);
    const float* src;
    if (m == 0) src = Wq; else if (m == 1) src = Wk; else if (m == 2) src = Wv; else src = Wo;
    float4 v = *(const float4*)(src + off);
    __nv_bfloat162 lo = __floats2bfloat162_rn(v.x, v.y);
    __nv_bfloat162 hi = __floats2bfloat162_rn(v.z, v.w);
    *(__nv_bfloat162*)(g_wb + idx)     = lo;
    *(__nv_bfloat162*)(g_wb + idx + 2) = hi;
}

// ---------------------------------------------------------------------------
// bf16 MMA GEMM: BM=128, BN=64, BK=32; 3-stage cp.async, 1 sync/iter
// ---------------------------------------------------------------------------
#define APAD 40
#define BPAD 72
#define NSTG 3

__device__ __forceinline__ void mma16(float* c, const uint32_t* a, const uint32_t* b) {
    asm volatile(
        "mma.sync.aligned.m16n8k16.row.col.f32.bf16.bf16.f32 "
        "{%0,%1,%2,%3}, {%4,%5,%6,%7}, {%8,%9}, {%0,%1,%2,%3};"
        : "+f"(c[0]), "+f"(c[1]), "+f"(c[2]), "+f"(c[3])
        : "r"(a[0]), "r"(a[1]), "r"(a[2]), "r"(a[3]), "r"(b[0]), "r"(b[1]));
}

template <bool RESID, bool BF16OUT>
__device__ __forceinline__ void gemm_bf16(const __nv_bfloat16* __restrict__ A,
                                          const __nv_bfloat16* __restrict__ Bm,
                                          const float* __restrict__ bias,
                                          const float* __restrict__ resid,
                                          void* __restrict__ Cv,
                                          float scale,
                                          int bx, int by) {
    const int K = D_, N = D_;
    __shared__ __nv_bfloat16 As[NSTG][128][APAD];
    __shared__ __nv_bfloat16 Bs[NSTG][32][BPAD];

    int tid = threadIdx.x;
    int lane = tid & 31, wid = tid >> 5;
    int wm = wid & 3, wn = wid >> 2;
    int m0 = by * 128, n0 = bx * 64;

    float acc[2][4][4];
    #pragma unroll
    for (int mt = 0; mt < 2; mt++)
        #pragma unroll
        for (int nt = 0; nt < 4; nt++)
            #pragma unroll
            for (int i = 0; i < 4; i++) acc[mt][nt][i] = 0.f;

    int ar = tid >> 2;
    int ac = (tid & 3) * 8;
    int br = tid >> 3;
    int bc = (tid & 7) * 8;

    uint32_t sA = smem_u32(&As[0][0][0]);
    uint32_t sB = smem_u32(&Bs[0][0][0]);
    const uint32_t ABUF = 128 * APAD * 2;
    const uint32_t BBUF = 32 * BPAD * 2;

    uint32_t dA0 = sA + (ar * APAD + ac) * 2;
    uint32_t dA1 = sA + ((ar + 64) * APAD + ac) * 2;
    uint32_t dB  = sB + (br * BPAD + bc) * 2;

    const __nv_bfloat16* gA0 = A + (size_t)(m0 + ar) * K + ac;
    const __nv_bfloat16* gA1 = A + (size_t)(m0 + ar + 64) * K + ac;
    const __nv_bfloat16* gB  = Bm + (size_t)br * N + n0 + bc;

    const int NIT = K / 32;   // 16
    // prologue: tiles 0,1
    #pragma unroll
    for (int s = 0; s < 2; s++) {
        int k0 = s * 32;
        CP_ASYNC16(dA0 + s * ABUF, gA0 + k0);
        CP_ASYNC16(dA1 + s * ABUF, gA1 + k0);
        CP_ASYNC16(dB  + s * BBUF, gB + (size_t)k0 * N);
        CP_COMMIT();
    }

    for (int it = 0; it < NIT; it++) {
        CP_WAIT(1);
        __syncthreads();
        if (it + 2 < NIT) {
            int sb = (it + 2) % NSTG;
            int k0 = (it + 2) * 32;
            CP_ASYNC16(dA0 + sb * ABUF, gA0 + k0);
            CP_ASYNC16(dA1 + sb * ABUF, gA1 + k0);
            CP_ASYNC16(dB  + sb * BBUF, gB + (size_t)k0 * N);
            CP_COMMIT();
        }
        int buf = it % NSTG;
        uint32_t aBase = sA + buf * ABUF;
        uint32_t bBase = sB + buf * BBUF;
        #pragma unroll
        for (int ks = 0; ks < 2; ks++) {
            int kq = ks * 16;
            uint32_t a[2][4], bf[2][4];
            #pragma unroll
            for (int mt = 0; mt < 2; mt++) {
                int row = wm * 32 + mt * 16 + (lane & 15);
                int col = kq + ((lane >> 4) * 8);
                uint32_t addr = aBase + (row * APAD + col) * 2;
                asm volatile("ldmatrix.sync.aligned.m8n8.x4.shared.b16 {%0,%1,%2,%3}, [%4];"
                             : "=r"(a[mt][0]), "=r"(a[mt][1]), "=r"(a[mt][2]), "=r"(a[mt][3])
                             : "r"(addr));
            }
            #pragma unroll
            for (int np = 0; np < 2; np++) {
                int row = kq + (lane & 15);
                int col = wn * 32 + np * 16 + ((lane >> 4) * 8);
                uint32_t addr = bBase + (row * BPAD + col) * 2;
                asm volatile("ldmatrix.sync.aligned.m8n8.x4.trans.shared.b16 {%0,%1,%2,%3}, [%4];"
                             : "=r"(bf[np][0]), "=r"(bf[np][1]), "=r"(bf[np][2]), "=r"(bf[np][3])
                             : "r"(addr));
            }
            #pragma unroll
            for (int mt = 0; mt < 2; mt++)
                #pragma unroll
                for (int nt = 0; nt < 4; nt++)
                    mma16(acc[mt][nt], a[mt], &bf[nt >> 1][(nt & 1) * 2]);
        }
        __syncthreads();   // protect buf reuse (stage written at it+3)
    }

    #pragma unroll
    for (int mt = 0; mt < 2; mt++) {
        #pragma unroll
        for (int nt = 0; nt < 4; nt++) {
            int r0 = m0 + wm * 32 + mt * 16 + (lane >> 2);
            int c  = n0 + wn * 32 + nt * 8 + (lane & 3) * 2;
            float b0 = bias[c], b1 = bias[c + 1];
            float o00 = (acc[mt][nt][0] + b0) * scale;
            float o01 = (acc[mt][nt][1] + b1) * scale;
            float o10 = (acc[mt][nt][2] + b0) * scale;
            float o11 = (acc[mt][nt][3] + b1) * scale;
            if (BF16OUT) {
                __nv_bfloat16* C = (__nv_bfloat16*)Cv;
                *(__nv_bfloat162*)(C + (size_t)r0 * D_ + c)       = __floats2bfloat162_rn(o00, o01);
                *(__nv_bfloat162*)(C + (size_t)(r0 + 8) * D_ + c) = __floats2bfloat162_rn(o10, o11);
            } else {
                float* C = (float*)Cv;
                if (RESID) {
                    float2 r0v = *(const float2*)(resid + (size_t)r0 * D_ + c);
                    float2 r1v = *(const float2*)(resid + (size_t)(r0 + 8) * D_ + c);
                    o00 += r0v.x; o01 += r0v.y;
                    o10 += r1v.x; o11 += r1v.y;
                }
                *(float2*)(C + (size_t)r0 * D_ + c)       = make_float2(o00, o01);
                *(float2*)(C + (size_t)(r0 + 8) * D_ + c) = make_float2(o10, o11);
            }
        }
    }
}

__global__ __launch_bounds__(256) void qkv_kernel(const float* __restrict__ bq,
                                                  const float* __restrict__ bk,
                                                  const float* __restrict__ bv) {
    const float* bi; __nv_bfloat16* C; float scale;
    if (blockIdx.z == 0)      { bi = bq; C = g_qb; scale = 0.125f; }
    else if (blockIdx.z == 1) { bi = bk; C = g_kb; scale = 1.f; }
    else                      { bi = bv; C = g_vb; scale = 1.f; }
    const __nv_bfloat16* W = g_wb + (size_t)blockIdx.z * D_ * D_;
    gemm_bf16<false, true>(g_hb, W, bi, nullptr, C, scale, blockIdx.x, blockIdx.y);
}

__global__ __launch_bounds__(256) void out_kernel(const float* __restrict__ bo,
                                                  const float* __restrict__ x,
                                                  float* __restrict__ out) {
    gemm_bf16<true, false>(g_ctxb, g_wb + (size_t)3 * D_ * D_, bo, x, out, 1.f,
                           blockIdx.x, blockIdx.y);
}

// ---------------------------------------------------------------------------
// 3) Banded attention: block = (b,h) x 64 queries, 512 threads (16 warps x 4q)
//    bf16 K/V window in SMEM; 8-lane groups, lane owns 8 dims (one uint4)
// ---------------------------------------------------------------------------
#define TQ 64
#define WROWS (TQ + 9)   // 73
#define KVP 72           // bf16 row stride (144B, 16B-aligned)

__global__ __launch_bounds__(512) void attn_kernel() {
    __shared__ __nv_bfloat16 Ks[WROWS][KVP];
    __shared__ __nv_bfloat16 Vs[WROWS][KVP];

    int bh = blockIdx.y;
    int b = bh >> 3, h = bh & 7;
    int t0 = blockIdx.x * TQ;
    int tid = threadIdx.x;

    // stage K/V: 73 rows x 8 uint4 each
    for (int idx = tid; idx < WROWS * 8; idx += 512) {
        int r = idx >> 3;
        int c = (idx & 7) * 8;           // bf16 col
        int jg = t0 - 6 + r;
        if (jg >= 0 && jg < T_) {
            size_t base = ((size_t)(b * T_ + jg)) * D_ + h * DH_ + c;
            *(uint4*)&Ks[r][c] = *(const uint4*)(g_kb + base);
            *(uint4*)&Vs[r][c] = *(const uint4*)(g_vb + base);
        } else {
            uint4 z = make_uint4(0, 0, 0, 0);
            *(uint4*)&Ks[r][c] = z;
            *(uint4*)&Vs[r][c] = z;
        }
    }
    __syncthreads();

    int w = tid >> 5, lane = tid & 31;
    int sub = lane >> 3, di = lane & 7;
    int t = t0 + w * 4 + sub;
    int lo = max(t - 6, 0);
    int hi = min(t + 3, T_ - 1);
    int nw = hi - lo + 1;
    int rbase = lo - (t0 - 6);

    // q (already scaled by 1/8): 8 bf16
    const __nv_bfloat16* qp = g_qb + ((size_t)(b * T_ + t)) * D_ + h * DH_ + di * 8;
    uint4 qu = *(const uint4*)qp;
    float2 q01 = __bfloat1622float2(*(__nv_bfloat162*)&qu.x);
    float2 q23 = __bfloat1622float2(*(__nv_bfloat162*)&qu.y);
    float2 q45 = __bfloat1622float2(*(__nv_bfloat162*)&qu.z);
    float2 q67 = __bfloat1622float2(*(__nv_bfloat162*)&qu.w);

    float sc[10];
    float mx = -1e30f;
    #pragma unroll
    for (int jj = 0; jj < 10; jj++) {
        int r = rbase + jj;
        uint4 ku = *(const uint4*)&Ks[r][di * 8];
        float2 k01 = __bfloat1622float2(*(__nv_bfloat162*)&ku.x);
        float2 k23 = __bfloat1622float2(*(__nv_bfloat162*)&ku.y);
        float2 k45 = __bfloat1622float2(*(__nv_bfloat162*)&ku.z);
        float2 k67 = __bfloat1622float2(*(__nv_bfloat162*)&ku.w);
        float s = q01.x * k01.x + q01.y * k01.y + q23.x * k23.x + q23.y * k23.y
                + q45.x * k45.x + q45.y * k45.y + q67.x * k67.x + q67.y * k67.y;
        s += __shfl_xor_sync(0xFFFFFFFFu, s, 4);
        s += __shfl_xor_sync(0xFFFFFFFFu, s, 2);
        s += __shfl_xor_sync(0xFFFFFFFFu, s, 1);
        s = (jj < nw) ? s : -1e30f;
        sc[jj] = s;
        mx = fmaxf(mx, s);
    }

    float denom = 0.f;
    float a0 = 0.f, a1 = 0.f, a2 = 0.f, a3 = 0.f;
    float a4 = 0.f, a5 = 0.f, a6 = 0.f, a7 = 0.f;
    #pragma unroll
    for (int jj = 0; jj < 10; jj++) {
        float p = __expf(sc[jj] - mx);
        denom += p;
        int r = rbase + jj;
        uint4 vu = *(const uint4*)&Vs[r][di * 8];
        float2 v01 = __bfloat1622float2(*(__nv_bfloat162*)&vu.x);
        float2 v23 = __bfloat1622float2(*(__nv_bfloat162*)&vu.y);
        float2 v45 = __bfloat1622float2(*(__nv_bfloat162*)&vu.z);
        float2 v67 = __bfloat1622float2(*(__nv_bfloat162*)&vu.w);
        a0 = fmaf(p, v01.x, a0); a1 = fmaf(p, v01.y, a1);
        a2 = fmaf(p, v23.x, a2); a3 = fmaf(p, v23.y, a3);
        a4 = fmaf(p, v45.x, a4); a5 = fmaf(p, v45.y, a5);
        a6 = fmaf(p, v67.x, a6); a7 = fmaf(p, v67.y, a7);
    }
    float inv = 1.f / denom;

    __nv_bfloat162 o0 = __floats2bfloat162_rn(a0 * inv, a1 * inv);
    __nv_bfloat162 o1 = __floats2bfloat162_rn(a2 * inv, a3 * inv);
    __nv_bfloat162 o2 = __floats2bfloat162_rn(a4 * inv, a5 * inv);
    __nv_bfloat162 o3 = __floats2bfloat162_rn(a6 * inv, a7 * inv);
    uint4 pack;
    pack.x = *(uint32_t*)&o0; pack.y = *(uint32_t*)&o1;
    pack.z = *(uint32_t*)&o2; pack.w = *(uint32_t*)&o3;
    *(uint4*)(g_ctxb + ((size_t)(b * T_ + t)) * D_ + h * DH_ + di * 8) = pack;
}

// ---------------------------------------------------------------------------
// Launch
// ---------------------------------------------------------------------------
extern "C" void kernel_launch(void* const* d_in, const int* in_sizes, int n_in,
                              void* d_out, int out_size) {
    const float* x     = (const float*)d_in[0];
    const float* gamma = (const float*)d_in[1];
    const float* beta  = (const float*)d_in[2];
    const float* Wq    = (const float*)d_in[3];
    const float* bq    = (const float*)d_in[4];
    const float* Wk    = (const float*)d_in[5];
    const float* bk    = (const float*)d_in[6];
    const float* Wv    = (const float*)d_in[7];
    const float* bv    = (const float*)d_in[8];
    const float* Wo    = (const float*)d_in[9];
    const float* bo    = (const float*)d_in[10];
    float* out = (float*)d_out;

    conv_kernel<<<(4 * D_ * D_) / (256 * 4), 256>>>(Wq, Wk, Wv, Wo);
    ln_kernel<<<M_, 256>>>(x, gamma, beta);
    qkv_kernel<<<dim3(D_/64, M_/128, 3), 256>>>(bq, bk, bv);
    attn_kernel<<<dim3(T_/TQ, B_*H_), 512>>>();
    out_kernel<<<dim3(D_/64, M_/128), 256>>>(bo, x, out);
}

// round 6
// speedup vs baseline: 1.2972x; 1.2972x over previous
#include <cuda_runtime.h>
#include <cuda_bf16.h>
#include <math.h>
#include <stdint.h>

#define B_   2
#define T_   2048
#define D_   512
#define H_   8
#define DH_  64
#define M_   (B_*T_)   // 4096 token rows

// Scratch (no cudaMalloc allowed)
__device__ __nv_bfloat16 g_hb[M_*D_];        // LN output, bf16
__device__ __nv_bfloat16 g_wb[4*D_*D_];      // bf16 weights: q,k,v,o
__device__ __nv_bfloat16 g_qb[M_*D_];        // q (pre-scaled by 1/8), bf16
__device__ __nv_bfloat16 g_kb[M_*D_];
__device__ __nv_bfloat16 g_vb[M_*D_];
__device__ __nv_bfloat16 g_ctxb[M_*D_];      // attention output, bf16

__device__ __forceinline__ uint32_t smem_u32(const void* p) {
    return (uint32_t)__cvta_generic_to_shared(p);
}

#define CP_ASYNC16(dst, src) \
    asm volatile("cp.async.cg.shared.global [%0], [%1], 16;" :: "r"(dst), "l"(src))
#define CP_COMMIT() asm volatile("cp.async.commit_group;")
#define CP_WAIT(n)  asm volatile("cp.async.wait_group %0;" :: "n"(n))

// ---------------------------------------------------------------------------
// 1) LayerNorm -> bf16 h
// ---------------------------------------------------------------------------
__global__ __launch_bounds__(256) void ln_kernel(const float* __restrict__ x,
                                                 const float* __restrict__ gamma,
                                                 const float* __restrict__ beta) {
    int row = blockIdx.x;
    int tid = threadIdx.x;
    const float* xr = x + (size_t)row * D_;
    float v0 = xr[tid], v1 = xr[tid + 256];
    float s  = v0 + v1;
    float s2 = v0 * v0 + v1 * v1;
    #pragma unroll
    for (int o = 16; o > 0; o >>= 1) {
        s  += __shfl_xor_sync(0xFFFFFFFFu, s,  o);
        s2 += __shfl_xor_sync(0xFFFFFFFFu, s2, o);
    }
    __shared__ float rs[8], rs2[8];
    int wid = tid >> 5, lane = tid & 31;
    if (lane == 0) { rs[wid] = s; rs2[wid] = s2; }
    __syncthreads();
    if (wid == 0) {
        s  = (lane < 8) ? rs[lane]  : 0.f;
        s2 = (lane < 8) ? rs2[lane] : 0.f;
        #pragma unroll
        for (int o = 4; o > 0; o >>= 1) {
            s  += __shfl_xor_sync(0xFFFFFFFFu, s,  o);
            s2 += __shfl_xor_sync(0xFFFFFFFFu, s2, o);
        }
        if (lane == 0) { rs[0] = s; rs2[0] = s2; }
    }
    __syncthreads();
    float mean = rs[0] * (1.0f / D_);
    float var  = rs2[0] * (1.0f / D_) - mean * mean;
    float rstd = rsqrtf(var + 1e-3f);
    __nv_bfloat16* hr = g_hb + (size_t)row * D_;
    hr[tid]       = __float2bfloat16_rn((v0 - mean) * rstd * gamma[tid]       + beta[tid]);
    hr[tid + 256] = __float2bfloat16_rn((v1 - mean) * rstd * gamma[tid + 256] + beta[tid + 256]);
}

// ---------------------------------------------------------------------------
// 1b) Weight conversion fp32 -> bf16
// ---------------------------------------------------------------------------
__global__ __launch_bounds__(256) void conv_kernel(const float* __restrict__ Wq,
                                                   const float* __restrict__ Wk,
                                                   const float* __restrict__ Wv,
                                                   const float* __restrict__ Wo) {
    size_t idx = ((size_t)blockIdx.x * 256 + threadIdx.x) * 4;
    int m = (int)(idx >> 18);
    size_t off = idx & ((1u << 18) - 1);
    const float* src;
    if (m == 0) src = Wq; else if (m == 1) src = Wk; else if (m == 2) src = Wv; else src = Wo;
    float4 v = *(const float4*)(src + off);
    __nv_bfloat162 lo = __floats2bfloat162_rn(v.x, v.y);
    __nv_bfloat162 hi = __floats2bfloat162_rn(v.z, v.w);
    *(__nv_bfloat162*)(g_wb + idx)     = lo;
    *(__nv_bfloat162*)(g_wb + idx + 2) = hi;
}

// ---------------------------------------------------------------------------
// bf16 MMA GEMM (R4 structure: 2-stage cp.async double buffer)
// BM=128, BN=64, BK=32; 8 warps, warp tile 32x32; m16n8k16
// ---------------------------------------------------------------------------
#define APAD 40
#define BPAD 72

__device__ __forceinline__ void mma16(float* c, const uint32_t* a, const uint32_t* b) {
    asm volatile(
        "mma.sync.aligned.m16n8k16.row.col.f32.bf16.bf16.f32 "
        "{%0,%1,%2,%3}, {%4,%5,%6,%7}, {%8,%9}, {%0,%1,%2,%3};"
        : "+f"(c[0]), "+f"(c[1]), "+f"(c[2]), "+f"(c[3])
        : "r"(a[0]), "r"(a[1]), "r"(a[2]), "r"(a[3]), "r"(b[0]), "r"(b[1]));
}

template <bool RESID, bool BF16OUT>
__device__ __forceinline__ void gemm_bf16(const __nv_bfloat16* __restrict__ A,
                                          const __nv_bfloat16* __restrict__ Bm,
                                          const float* __restrict__ bias,
                                          const float* __restrict__ resid,
                                          void* __restrict__ Cv,
                                          float scale,
                                          int bx, int by) {
    const int K = D_, N = D_;
    __shared__ __nv_bfloat16 As[2][128][APAD];
    __shared__ __nv_bfloat16 Bs[2][32][BPAD];

    int tid = threadIdx.x;
    int lane = tid & 31, wid = tid >> 5;
    int wm = wid & 3, wn = wid >> 2;
    int m0 = by * 128, n0 = bx * 64;

    float acc[2][4][4];
    #pragma unroll
    for (int mt = 0; mt < 2; mt++)
        #pragma unroll
        for (int nt = 0; nt < 4; nt++)
            #pragma unroll
            for (int i = 0; i < 4; i++) acc[mt][nt][i] = 0.f;

    int ar = tid >> 2;
    int ac = (tid & 3) * 8;
    int br = tid >> 3;
    int bc = (tid & 7) * 8;

    uint32_t sA = smem_u32(&As[0][0][0]);
    uint32_t sB = smem_u32(&Bs[0][0][0]);
    const uint32_t ABUF = 128 * APAD * 2;
    const uint32_t BBUF = 32 * BPAD * 2;

    uint32_t dA0 = sA + (ar * APAD + ac) * 2;
    uint32_t dA1 = sA + ((ar + 64) * APAD + ac) * 2;
    uint32_t dB  = sB + (br * BPAD + bc) * 2;

    const __nv_bfloat16* gA0 = A + (size_t)(m0 + ar) * K + ac;
    const __nv_bfloat16* gA1 = A + (size_t)(m0 + ar + 64) * K + ac;
    const __nv_bfloat16* gB  = Bm + (size_t)br * N + n0 + bc;

    CP_ASYNC16(dA0, gA0);
    CP_ASYNC16(dA1, gA1);
    CP_ASYNC16(dB,  gB);
    CP_COMMIT();

    const int NIT = K / 32;
    for (int it = 0; it < NIT; it++) {
        int buf = it & 1;
        if (it + 1 < NIT) {
            int nb = (it + 1) & 1;
            int k0 = (it + 1) * 32;
            CP_ASYNC16(dA0 + nb * ABUF, gA0 + k0);
            CP_ASYNC16(dA1 + nb * ABUF, gA1 + k0);
            CP_ASYNC16(dB  + nb * BBUF, gB + (size_t)k0 * N);
            CP_COMMIT();
            CP_WAIT(1);
        } else {
            CP_WAIT(0);
        }
        __syncthreads();

        uint32_t aBase = sA + buf * ABUF;
        uint32_t bBase = sB + buf * BBUF;
        #pragma unroll
        for (int ks = 0; ks < 2; ks++) {
            int kq = ks * 16;
            uint32_t a[2][4], bf[2][4];
            #pragma unroll
            for (int mt = 0; mt < 2; mt++) {
                int row = wm * 32 + mt * 16 + (lane & 15);
                int col = kq + ((lane >> 4) * 8);
                uint32_t addr = aBase + (row * APAD + col) * 2;
                asm volatile("ldmatrix.sync.aligned.m8n8.x4.shared.b16 {%0,%1,%2,%3}, [%4];"
                             : "=r"(a[mt][0]), "=r"(a[mt][1]), "=r"(a[mt][2]), "=r"(a[mt][3])
                             : "r"(addr));
            }
            #pragma unroll
            for (int np = 0; np < 2; np++) {
                int row = kq + (lane & 15);
                int col = wn * 32 + np * 16 + ((lane >> 4) * 8);
                uint32_t addr = bBase + (row * BPAD + col) * 2;
                asm volatile("ldmatrix.sync.aligned.m8n8.x4.trans.shared.b16 {%0,%1,%2,%3}, [%4];"
                             : "=r"(bf[np][0]), "=r"(bf[np][1]), "=r"(bf[np][2]), "=r"(bf[np][3])
                             : "r"(addr));
            }
            #pragma unroll
            for (int mt = 0; mt < 2; mt++)
                #pragma unroll
                for (int nt = 0; nt < 4; nt++)
                    mma16(acc[mt][nt], a[mt], &bf[nt >> 1][(nt & 1) * 2]);
        }
        __syncthreads();
    }

    #pragma unroll
    for (int mt = 0; mt < 2; mt++) {
        #pragma unroll
        for (int nt = 0; nt < 4; nt++) {
            int r0 = m0 + wm * 32 + mt * 16 + (lane >> 2);
            int c  = n0 + wn * 32 + nt * 8 + (lane & 3) * 2;
            float b0 = bias[c], b1 = bias[c + 1];
            float o00 = (acc[mt][nt][0] + b0) * scale;
            float o01 = (acc[mt][nt][1] + b1) * scale;
            float o10 = (acc[mt][nt][2] + b0) * scale;
            float o11 = (acc[mt][nt][3] + b1) * scale;
            if (BF16OUT) {
                __nv_bfloat16* C = (__nv_bfloat16*)Cv;
                *(__nv_bfloat162*)(C + (size_t)r0 * D_ + c)       = __floats2bfloat162_rn(o00, o01);
                *(__nv_bfloat162*)(C + (size_t)(r0 + 8) * D_ + c) = __floats2bfloat162_rn(o10, o11);
            } else {
                float* C = (float*)Cv;
                if (RESID) {
                    float2 r0v = *(const float2*)(resid + (size_t)r0 * D_ + c);
                    float2 r1v = *(const float2*)(resid + (size_t)(r0 + 8) * D_ + c);
                    o00 += r0v.x; o01 += r0v.y;
                    o10 += r1v.x; o11 += r1v.y;
                }
                *(float2*)(C + (size_t)r0 * D_ + c)       = make_float2(o00, o01);
                *(float2*)(C + (size_t)(r0 + 8) * D_ + c) = make_float2(o10, o11);
            }
        }
    }
}

__global__ __launch_bounds__(256) void qkv_kernel(const float* __restrict__ bq,
                                                  const float* __restrict__ bk,
                                                  const float* __restrict__ bv) {
    const float* bi; __nv_bfloat16* C; float scale;
    if (blockIdx.z == 0)      { bi = bq; C = g_qb; scale = 0.125f; }
    else if (blockIdx.z == 1) { bi = bk; C = g_kb; scale = 1.f; }
    else                      { bi = bv; C = g_vb; scale = 1.f; }
    const __nv_bfloat16* W = g_wb + (size_t)blockIdx.z * D_ * D_;
    gemm_bf16<false, true>(g_hb, W, bi, nullptr, C, scale, blockIdx.x, blockIdx.y);
}

__global__ __launch_bounds__(256) void out_kernel(const float* __restrict__ bo,
                                                  const float* __restrict__ x,
                                                  float* __restrict__ out) {
    gemm_bf16<true, false>(g_ctxb, g_wb + (size_t)3 * D_ * D_, bo, x, out, 1.f,
                           blockIdx.x, blockIdx.y);
}

// ---------------------------------------------------------------------------
// 3) Banded attention (R4 shape): block = (b,h) x 32 queries, 256 threads.
//    bf16 in GLOBAL (half traffic), fp32 in SMEM (convert once on staging),
//    hot loops pure FFMA. Warp = 4 queries via 8-lane groups.
// ---------------------------------------------------------------------------
#define TQ 32
#define WROWS (TQ + 9)   // 41
#define KVPAD 68

__global__ __launch_bounds__(256) void attn_kernel() {
    __shared__ float Ks[WROWS][KVPAD];
    __shared__ float Vs[WROWS][KVPAD];

    int bh = blockIdx.y;
    int b = bh >> 3, h = bh & 7;
    int t0 = blockIdx.x * TQ;
    int tid = threadIdx.x;

    // stage K/V: 41 rows x 8 uint4 (8 bf16 each) -> fp32 SMEM
    for (int idx = tid; idx < WROWS * 8; idx += 256) {
        int r = idx >> 3;
        int c = (idx & 7) * 8;
        int jg = t0 - 6 + r;
        if (jg >= 0 && jg < T_) {
            size_t base = ((size_t)(b * T_ + jg)) * D_ + h * DH_ + c;
            uint4 ku = *(const uint4*)(g_kb + base);
            uint4 vu = *(const uint4*)(g_vb + base);
            float2 f;
            f = __bfloat1622float2(*(__nv_bfloat162*)&ku.x); Ks[r][c+0]=f.x; Ks[r][c+1]=f.y;
            f = __bfloat1622float2(*(__nv_bfloat162*)&ku.y); Ks[r][c+2]=f.x; Ks[r][c+3]=f.y;
            f = __bfloat1622float2(*(__nv_bfloat162*)&ku.z); Ks[r][c+4]=f.x; Ks[r][c+5]=f.y;
            f = __bfloat1622float2(*(__nv_bfloat162*)&ku.w); Ks[r][c+6]=f.x; Ks[r][c+7]=f.y;
            f = __bfloat1622float2(*(__nv_bfloat162*)&vu.x); Vs[r][c+0]=f.x; Vs[r][c+1]=f.y;
            f = __bfloat1622float2(*(__nv_bfloat162*)&vu.y); Vs[r][c+2]=f.x; Vs[r][c+3]=f.y;
            f = __bfloat1622float2(*(__nv_bfloat162*)&vu.z); Vs[r][c+4]=f.x; Vs[r][c+5]=f.y;
            f = __bfloat1622float2(*(__nv_bfloat162*)&vu.w); Vs[r][c+6]=f.x; Vs[r][c+7]=f.y;
        } else {
            float4 z = make_float4(0.f, 0.f, 0.f, 0.f);
            *(float4*)&Ks[r][c] = z; *(float4*)&Ks[r][c + 4] = z;
            *(float4*)&Vs[r][c] = z; *(float4*)&Vs[r][c + 4] = z;
        }
    }
    __syncthreads();

    int w = tid >> 5, lane = tid & 31;
    int sub = lane >> 3, di = lane & 7;
    int t = t0 + w * 4 + sub;
    int lo = max(t - 6, 0);
    int hi = min(t + 3, T_ - 1);
    int nw = hi - lo + 1;
    int rbase = lo - (t0 - 6);

    // q (already scaled by 1/8): 8 bf16 -> fp32 regs
    const __nv_bfloat16* qp = g_qb + ((size_t)(b * T_ + t)) * D_ + h * DH_ + di * 8;
    uint4 qu = *(const uint4*)qp;
    float2 q01 = __bfloat1622float2(*(__nv_bfloat162*)&qu.x);
    float2 q23 = __bfloat1622float2(*(__nv_bfloat162*)&qu.y);
    float2 q45 = __bfloat1622float2(*(__nv_bfloat162*)&qu.z);
    float2 q67 = __bfloat1622float2(*(__nv_bfloat162*)&qu.w);

    float sc[10];
    float mx = -1e30f;
    #pragma unroll
    for (int jj = 0; jj < 10; jj++) {
        int r = rbase + jj;
        const float* kr = &Ks[r][di * 8];
        float4 k0 = *(const float4*)kr;
        float4 k1 = *(const float4*)(kr + 4);
        float s = q01.x * k0.x + q01.y * k0.y + q23.x * k0.z + q23.y * k0.w
                + q45.x * k1.x + q45.y * k1.y + q67.x * k1.z + q67.y * k1.w;
        s += __shfl_xor_sync(0xFFFFFFFFu, s, 4);
        s += __shfl_xor_sync(0xFFFFFFFFu, s, 2);
        s += __shfl_xor_sync(0xFFFFFFFFu, s, 1);
        s = (jj < nw) ? s : -1e30f;
        sc[jj] = s;
        mx = fmaxf(mx, s);
    }

    float denom = 0.f;
    float a0 = 0.f, a1 = 0.f, a2 = 0.f, a3 = 0.f;
    float a4 = 0.f, a5 = 0.f, a6 = 0.f, a7 = 0.f;
    #pragma unroll
    for (int jj = 0; jj < 10; jj++) {
        float p = __expf(sc[jj] - mx);
        denom += p;
        int r = rbase + jj;
        const float* vr = &Vs[r][di * 8];
        float4 v0 = *(const float4*)vr;
        float4 v1 = *(const float4*)(vr + 4);
        a0 = fmaf(p, v0.x, a0); a1 = fmaf(p, v0.y, a1);
        a2 = fmaf(p, v0.z, a2); a3 = fmaf(p, v0.w, a3);
        a4 = fmaf(p, v1.x, a4); a5 = fmaf(p, v1.y, a5);
        a6 = fmaf(p, v1.z, a6); a7 = fmaf(p, v1.w, a7);
    }
    float inv = 1.f / denom;

    __nv_bfloat162 o0 = __floats2bfloat162_rn(a0 * inv, a1 * inv);
    __nv_bfloat162 o1 = __floats2bfloat162_rn(a2 * inv, a3 * inv);
    __nv_bfloat162 o2 = __floats2bfloat162_rn(a4 * inv, a5 * inv);
    __nv_bfloat162 o3 = __floats2bfloat162_rn(a6 * inv, a7 * inv);
    uint4 pack;
    pack.x = *(uint32_t*)&o0; pack.y = *(uint32_t*)&o1;
    pack.z = *(uint32_t*)&o2; pack.w = *(uint32_t*)&o3;
    *(uint4*)(g_ctxb + ((size_t)(b * T_ + t)) * D_ + h * DH_ + di * 8) = pack;
}

// ---------------------------------------------------------------------------
// Launch
// ---------------------------------------------------------------------------
extern "C" void kernel_launch(void* const* d_in, const int* in_sizes, int n_in,
                              void* d_out, int out_size) {
    const float* x     = (const float*)d_in[0];
    const float* gamma = (const float*)d_in[1];
    const float* beta  = (const float*)d_in[2];
    const float* Wq    = (const float*)d_in[3];
    const float* bq    = (const float*)d_in[4];
    const float* Wk    = (const float*)d_in[5];
    const float* bk    = (const float*)d_in[6];
    const float* Wv    = (const float*)d_in[7];
    const float* bv    = (const float*)d_in[8];
    const float* Wo    = (const float*)d_in[9];
    const float* bo    = (const float*)d_in[10];
    float* out = (float*)d_out;

    conv_kernel<<<(4 * D_ * D_) / (256 * 4), 256>>>(Wq, Wk, Wv, Wo);
    ln_kernel<<<M_, 256>>>(x, gamma, beta);
    qkv_kernel<<<dim3(D_/64, M_/128, 3), 256>>>(bq, bk, bv);
    attn_kernel<<<dim3(T_/TQ, B_*H_), 256>>>();
    out_kernel<<<dim3(D_/64, M_/128), 256>>>(bo, x, out);
}

// round 7
// speedup vs baseline: 1.3726x; 1.0581x over previous
#include <cuda_runtime.h>
#include <cuda_bf16.h>
#include <math.h>
#include <stdint.h>

#define B_   2
#define T_   2048
#define D_   512
#define H_   8
#define DH_  64
#define M_   (B_*T_)   // 4096 token rows

// Scratch (no cudaMalloc allowed)
__device__ __nv_bfloat16 g_hb[M_*D_];        // LN output, bf16
__device__ __nv_bfloat16 g_wb[4*D_*D_];      // bf16 weights: q,k,v,o
__device__ __nv_bfloat16 g_qb[M_*D_];        // q (pre-scaled by 1/8), bf16
__device__ __nv_bfloat16 g_kb[M_*D_];
__device__ __nv_bfloat16 g_vb[M_*D_];
__device__ __nv_bfloat16 g_ctxb[M_*D_];      // attention output, bf16

__device__ __forceinline__ uint32_t smem_u32(const void* p) {
    return (uint32_t)__cvta_generic_to_shared(p);
}

#define CP_ASYNC16(dst, src) \
    asm volatile("cp.async.cg.shared.global [%0], [%1], 16;" :: "r"(dst), "l"(src))
#define CP_COMMIT() asm volatile("cp.async.commit_group;")
#define CP_WAIT(n)  asm volatile("cp.async.wait_group %0;" :: "n"(n))

// ---------------------------------------------------------------------------
// 1) LayerNorm -> bf16 h : 128 threads/row, float4 loads
// ---------------------------------------------------------------------------
__global__ __launch_bounds__(128) void ln_kernel(const float* __restrict__ x,
                                                 const float* __restrict__ gamma,
                                                 const float* __restrict__ beta) {
    int row = blockIdx.x;
    int tid = threadIdx.x;
    const float4* xr = (const float4*)(x + (size_t)row * D_);
    float4 v = xr[tid];
    float s  = v.x + v.y + v.z + v.w;
    float s2 = v.x * v.x + v.y * v.y + v.z * v.z + v.w * v.w;
    #pragma unroll
    for (int o = 16; o > 0; o >>= 1) {
        s  += __shfl_xor_sync(0xFFFFFFFFu, s,  o);
        s2 += __shfl_xor_sync(0xFFFFFFFFu, s2, o);
    }
    __shared__ float rs[4], rs2[4];
    int wid = tid >> 5, lane = tid & 31;
    if (lane == 0) { rs[wid] = s; rs2[wid] = s2; }
    __syncthreads();
    s  = rs[0]  + rs[1]  + rs[2]  + rs[3];
    s2 = rs2[0] + rs2[1] + rs2[2] + rs2[3];
    float mean = s * (1.0f / D_);
    float var  = s2 * (1.0f / D_) - mean * mean;
    float rstd = rsqrtf(var + 1e-3f);
    float4 g = ((const float4*)gamma)[tid];
    float4 bb = ((const float4*)beta)[tid];
    float o0 = (v.x - mean) * rstd * g.x + bb.x;
    float o1 = (v.y - mean) * rstd * g.y + bb.y;
    float o2 = (v.z - mean) * rstd * g.z + bb.z;
    float o3 = (v.w - mean) * rstd * g.w + bb.w;
    __nv_bfloat162 p0 = __floats2bfloat162_rn(o0, o1);
    __nv_bfloat162 p1 = __floats2bfloat162_rn(o2, o3);
    uint2 pack = make_uint2(*(uint32_t*)&p0, *(uint32_t*)&p1);
    *(uint2*)(g_hb + (size_t)row * D_ + tid * 4) = pack;
}

// ---------------------------------------------------------------------------
// 1b) Weight conversion fp32 -> bf16
// ---------------------------------------------------------------------------
__global__ __launch_bounds__(256) void conv_kernel(const float* __restrict__ Wq,
                                                   const float* __restrict__ Wk,
                                                   const float* __restrict__ Wv,
                                                   const float* __restrict__ Wo) {
    size_t idx = ((size_t)blockIdx.x * 256 + threadIdx.x) * 4;
    int m = (int)(idx >> 18);
    size_t off = idx & ((1u << 18) - 1);
    const float* src;
    if (m == 0) src = Wq; else if (m == 1) src = Wk; else if (m == 2) src = Wv; else src = Wo;
    float4 v = *(const float4*)(src + off);
    __nv_bfloat162 lo = __floats2bfloat162_rn(v.x, v.y);
    __nv_bfloat162 hi = __floats2bfloat162_rn(v.z, v.w);
    *(__nv_bfloat162*)(g_wb + idx)     = lo;
    *(__nv_bfloat162*)(g_wb + idx + 2) = hi;
}

// ---------------------------------------------------------------------------
// bf16 MMA GEMM: 2-stage cp.async double buffer, ONE sync per iter
// BM=128, BN=64, BK=32; 8 warps, warp tile 32x32; m16n8k16
// ---------------------------------------------------------------------------
#define APAD 40
#define BPAD 72

__device__ __forceinline__ void mma16(float* c, const uint32_t* a, const uint32_t* b) {
    asm volatile(
        "mma.sync.aligned.m16n8k16.row.col.f32.bf16.bf16.f32 "
        "{%0,%1,%2,%3}, {%4,%5,%6,%7}, {%8,%9}, {%0,%1,%2,%3};"
        : "+f"(c[0]), "+f"(c[1]), "+f"(c[2]), "+f"(c[3])
        : "r"(a[0]), "r"(a[1]), "r"(a[2]), "r"(a[3]), "r"(b[0]), "r"(b[1]));
}

template <bool RESID, bool BF16OUT>
__device__ __forceinline__ void gemm_bf16(const __nv_bfloat16* __restrict__ A,
                                          const __nv_bfloat16* __restrict__ Bm,
                                          const float* __restrict__ bias,
                                          const float* __restrict__ resid,
                                          void* __restrict__ Cv,
                                          float scale,
                                          int bx, int by) {
    const int K = D_, N = D_;
    __shared__ __nv_bfloat16 As[2][128][APAD];
    __shared__ __nv_bfloat16 Bs[2][32][BPAD];

    int tid = threadIdx.x;
    int lane = tid & 31, wid = tid >> 5;
    int wm = wid & 3, wn = wid >> 2;
    int m0 = by * 128, n0 = bx * 64;

    float acc[2][4][4];
    #pragma unroll
    for (int mt = 0; mt < 2; mt++)
        #pragma unroll
        for (int nt = 0; nt < 4; nt++)
            #pragma unroll
            for (int i = 0; i < 4; i++) acc[mt][nt][i] = 0.f;

    int ar = tid >> 2;
    int ac = (tid & 3) * 8;
    int br = tid >> 3;
    int bc = (tid & 7) * 8;

    uint32_t sA = smem_u32(&As[0][0][0]);
    uint32_t sB = smem_u32(&Bs[0][0][0]);
    const uint32_t ABUF = 128 * APAD * 2;
    const uint32_t BBUF = 32 * BPAD * 2;

    uint32_t dA0 = sA + (ar * APAD + ac) * 2;
    uint32_t dA1 = sA + ((ar + 64) * APAD + ac) * 2;
    uint32_t dB  = sB + (br * BPAD + bc) * 2;

    const __nv_bfloat16* gA0 = A + (size_t)(m0 + ar) * K + ac;
    const __nv_bfloat16* gA1 = A + (size_t)(m0 + ar + 64) * K + ac;
    const __nv_bfloat16* gB  = Bm + (size_t)br * N + n0 + bc;

    CP_ASYNC16(dA0, gA0);
    CP_ASYNC16(dA1, gA1);
    CP_ASYNC16(dB,  gB);
    CP_COMMIT();

    const int NIT = K / 32;
    for (int it = 0; it < NIT; it++) {
        int buf = it & 1;
        CP_WAIT(0);              // tile `it` resident
        __syncthreads();         // all warps done reading buf (it+1)&1 from iter it-1
        if (it + 1 < NIT) {      // prefetch next tile into the other buffer
            int nb = (it + 1) & 1;
            int k0 = (it + 1) * 32;
            CP_ASYNC16(dA0 + nb * ABUF, gA0 + k0);
            CP_ASYNC16(dA1 + nb * ABUF, gA1 + k0);
            CP_ASYNC16(dB  + nb * BBUF, gB + (size_t)k0 * N);
            CP_COMMIT();
        }

        uint32_t aBase = sA + buf * ABUF;
        uint32_t bBase = sB + buf * BBUF;
        #pragma unroll
        for (int ks = 0; ks < 2; ks++) {
            int kq = ks * 16;
            uint32_t a[2][4], bf[2][4];
            #pragma unroll
            for (int mt = 0; mt < 2; mt++) {
                int row = wm * 32 + mt * 16 + (lane & 15);
                int col = kq + ((lane >> 4) * 8);
                uint32_t addr = aBase + (row * APAD + col) * 2;
                asm volatile("ldmatrix.sync.aligned.m8n8.x4.shared.b16 {%0,%1,%2,%3}, [%4];"
                             : "=r"(a[mt][0]), "=r"(a[mt][1]), "=r"(a[mt][2]), "=r"(a[mt][3])
                             : "r"(addr));
            }
            #pragma unroll
            for (int np = 0; np < 2; np++) {
                int row = kq + (lane & 15);
                int col = wn * 32 + np * 16 + ((lane >> 4) * 8);
                uint32_t addr = bBase + (row * BPAD + col) * 2;
                asm volatile("ldmatrix.sync.aligned.m8n8.x4.trans.shared.b16 {%0,%1,%2,%3}, [%4];"
                             : "=r"(bf[np][0]), "=r"(bf[np][1]), "=r"(bf[np][2]), "=r"(bf[np][3])
                             : "r"(addr));
            }
            #pragma unroll
            for (int mt = 0; mt < 2; mt++)
                #pragma unroll
                for (int nt = 0; nt < 4; nt++)
                    mma16(acc[mt][nt], a[mt], &bf[nt >> 1][(nt & 1) * 2]);
        }
    }

    #pragma unroll
    for (int mt = 0; mt < 2; mt++) {
        #pragma unroll
        for (int nt = 0; nt < 4; nt++) {
            int r0 = m0 + wm * 32 + mt * 16 + (lane >> 2);
            int c  = n0 + wn * 32 + nt * 8 + (lane & 3) * 2;
            float b0 = bias[c], b1 = bias[c + 1];
            float o00 = (acc[mt][nt][0] + b0) * scale;
            float o01 = (acc[mt][nt][1] + b1) * scale;
            float o10 = (acc[mt][nt][2] + b0) * scale;
            float o11 = (acc[mt][nt][3] + b1) * scale;
            if (BF16OUT) {
                __nv_bfloat16* C = (__nv_bfloat16*)Cv;
                *(__nv_bfloat162*)(C + (size_t)r0 * D_ + c)       = __floats2bfloat162_rn(o00, o01);
                *(__nv_bfloat162*)(C + (size_t)(r0 + 8) * D_ + c) = __floats2bfloat162_rn(o10, o11);
            } else {
                float* C = (float*)Cv;
                if (RESID) {
                    float2 r0v = *(const float2*)(resid + (size_t)r0 * D_ + c);
                    float2 r1v = *(const float2*)(resid + (size_t)(r0 + 8) * D_ + c);
                    o00 += r0v.x; o01 += r0v.y;
                    o10 += r1v.x; o11 += r1v.y;
                }
                *(float2*)(C + (size_t)r0 * D_ + c)       = make_float2(o00, o01);
                *(float2*)(C + (size_t)(r0 + 8) * D_ + c) = make_float2(o10, o11);
            }
        }
    }
}

__global__ __launch_bounds__(256) void qkv_kernel(const float* __restrict__ bq,
                                                  const float* __restrict__ bk,
                                                  const float* __restrict__ bv) {
    const float* bi; __nv_bfloat16* C; float scale;
    if (blockIdx.z == 0)      { bi = bq; C = g_qb; scale = 0.125f; }
    else if (blockIdx.z == 1) { bi = bk; C = g_kb; scale = 1.f; }
    else                      { bi = bv; C = g_vb; scale = 1.f; }
    const __nv_bfloat16* W = g_wb + (size_t)blockIdx.z * D_ * D_;
    gemm_bf16<false, true>(g_hb, W, bi, nullptr, C, scale, blockIdx.x, blockIdx.y);
}

__global__ __launch_bounds__(256) void out_kernel(const float* __restrict__ bo,
                                                  const float* __restrict__ x,
                                                  float* __restrict__ out) {
    gemm_bf16<true, false>(g_ctxb, g_wb + (size_t)3 * D_ * D_, bo, x, out, 1.f,
                           blockIdx.x, blockIdx.y);
}

// ---------------------------------------------------------------------------
// 3) Banded attention: block = (b,h) x 32 queries, 256 threads.
//    bf16 global loads, fp32 SMEM (converted once, float4 STS), FFMA hot loop.
// ---------------------------------------------------------------------------
#define TQ 32
#define WROWS (TQ + 9)   // 41
#define KVPAD 68

__global__ __launch_bounds__(256) void attn_kernel() {
    __shared__ float Ks[WROWS][KVPAD];
    __shared__ float Vs[WROWS][KVPAD];

    int bh = blockIdx.y;
    int b = bh >> 3, h = bh & 7;
    int t0 = blockIdx.x * TQ;
    int tid = threadIdx.x;

    // stage K/V: 41 rows x 8 uint4 (8 bf16) -> fp32 SMEM via float4 stores
    for (int idx = tid; idx < WROWS * 8; idx += 256) {
        int r = idx >> 3;
        int c = (idx & 7) * 8;
        int jg = t0 - 6 + r;
        if (jg >= 0 && jg < T_) {
            size_t base = ((size_t)(b * T_ + jg)) * D_ + h * DH_ + c;
            uint4 ku = *(const uint4*)(g_kb + base);
            uint4 vu = *(const uint4*)(g_vb + base);
            float2 k01 = __bfloat1622float2(*(__nv_bfloat162*)&ku.x);
            float2 k23 = __bfloat1622float2(*(__nv_bfloat162*)&ku.y);
            float2 k45 = __bfloat1622float2(*(__nv_bfloat162*)&ku.z);
            float2 k67 = __bfloat1622float2(*(__nv_bfloat162*)&ku.w);
            *(float4*)&Ks[r][c]     = make_float4(k01.x, k01.y, k23.x, k23.y);
            *(float4*)&Ks[r][c + 4] = make_float4(k45.x, k45.y, k67.x, k67.y);
            float2 v01 = __bfloat1622float2(*(__nv_bfloat162*)&vu.x);
            float2 v23 = __bfloat1622float2(*(__nv_bfloat162*)&vu.y);
            float2 v45 = __bfloat1622float2(*(__nv_bfloat162*)&vu.z);
            float2 v67 = __bfloat1622float2(*(__nv_bfloat162*)&vu.w);
            *(float4*)&Vs[r][c]     = make_float4(v01.x, v01.y, v23.x, v23.y);
            *(float4*)&Vs[r][c + 4] = make_float4(v45.x, v45.y, v67.x, v67.y);
        } else {
            float4 z = make_float4(0.f, 0.f, 0.f, 0.f);
            *(float4*)&Ks[r][c] = z; *(float4*)&Ks[r][c + 4] = z;
            *(float4*)&Vs[r][c] = z; *(float4*)&Vs[r][c + 4] = z;
        }
    }
    __syncthreads();

    int w = tid >> 5, lane = tid & 31;
    int sub = lane >> 3, di = lane & 7;
    int t = t0 + w * 4 + sub;
    int lo = max(t - 6, 0);
    int hi = min(t + 3, T_ - 1);
    int nw = hi - lo + 1;
    int rbase = lo - (t0 - 6);

    // q (already scaled by 1/8): 8 bf16 -> fp32 regs
    const __nv_bfloat16* qp = g_qb + ((size_t)(b * T_ + t)) * D_ + h * DH_ + di * 8;
    uint4 qu = *(const uint4*)qp;
    float2 q01 = __bfloat1622float2(*(__nv_bfloat162*)&qu.x);
    float2 q23 = __bfloat1622float2(*(__nv_bfloat162*)&qu.y);
    float2 q45 = __bfloat1622float2(*(__nv_bfloat162*)&qu.z);
    float2 q67 = __bfloat1622float2(*(__nv_bfloat162*)&qu.w);

    float sc[10];
    float mx = -1e30f;
    #pragma unroll
    for (int jj = 0; jj < 10; jj++) {
        int r = rbase + jj;
        const float* kr = &Ks[r][di * 8];
        float4 k0 = *(const float4*)kr;
        float4 k1 = *(const float4*)(kr + 4);
        float s = q01.x * k0.x + q01.y * k0.y + q23.x * k0.z + q23.y * k0.w
                + q45.x * k1.x + q45.y * k1.y + q67.x * k1.z + q67.y * k1.w;
        s += __shfl_xor_sync(0xFFFFFFFFu, s, 4);
        s += __shfl_xor_sync(0xFFFFFFFFu, s, 2);
        s += __shfl_xor_sync(0xFFFFFFFFu, s, 1);
        s = (jj < nw) ? s : -1e30f;
        sc[jj] = s;
        mx = fmaxf(mx, s);
    }

    float denom = 0.f;
    float a0 = 0.f, a1 = 0.f, a2 = 0.f, a3 = 0.f;
    float a4 = 0.f, a5 = 0.f, a6 = 0.f, a7 = 0.f;
    #pragma unroll
    for (int jj = 0; jj < 10; jj++) {
        float p = __expf(sc[jj] - mx);
        denom += p;
        int r = rbase + jj;
        const float* vr = &Vs[r][di * 8];
        float4 v0 = *(const float4*)vr;
        float4 v1 = *(const float4*)(vr + 4);
        a0 = fmaf(p, v0.x, a0); a1 = fmaf(p, v0.y, a1);
        a2 = fmaf(p, v0.z, a2); a3 = fmaf(p, v0.w, a3);
        a4 = fmaf(p, v1.x, a4); a5 = fmaf(p, v1.y, a5);
        a6 = fmaf(p, v1.z, a6); a7 = fmaf(p, v1.w, a7);
    }
    float inv = 1.f / denom;

    __nv_bfloat162 o0 = __floats2bfloat162_rn(a0 * inv, a1 * inv);
    __nv_bfloat162 o1 = __floats2bfloat162_rn(a2 * inv, a3 * inv);
    __nv_bfloat162 o2 = __floats2bfloat162_rn(a4 * inv, a5 * inv);
    __nv_bfloat162 o3 = __floats2bfloat162_rn(a6 * inv, a7 * inv);
    uint4 pack;
    pack.x = *(uint32_t*)&o0; pack.y = *(uint32_t*)&o1;
    pack.z = *(uint32_t*)&o2; pack.w = *(uint32_t*)&o3;
    *(uint4*)(g_ctxb + ((size_t)(b * T_ + t)) * D_ + h * DH_ + di * 8) = pack;
}

// ---------------------------------------------------------------------------
// Launch
// ---------------------------------------------------------------------------
extern "C" void kernel_launch(void* const* d_in, const int* in_sizes, int n_in,
                              void* d_out, int out_size) {
    const float* x     = (const float*)d_in[0];
    const float* gamma = (const float*)d_in[1];
    const float* beta  = (const float*)d_in[2];
    const float* Wq    = (const float*)d_in[3];
    const float* bq    = (const float*)d_in[4];
    const float* Wk    = (const float*)d_in[5];
    const float* bk    = (const float*)d_in[6];
    const float* Wv    = (const float*)d_in[7];
    const float* bv    = (const float*)d_in[8];
    const float* Wo    = (const float*)d_in[9];
    const float* bo    = (const float*)d_in[10];
    float* out = (float*)d_out;

    conv_kernel<<<(4 * D_ * D_) / (256 * 4), 256>>>(Wq, Wk, Wv, Wo);
    ln_kernel<<<M_, 128>>>(x, gamma, beta);
    qkv_kernel<<<dim3(D_/64, M_/128, 3), 256>>>(bq, bk, bv);
    attn_kernel<<<dim3(T_/TQ, B_*H_), 256>>>();
    out_kernel<<<dim3(D_/64, M_/128), 256>>>(bo, x, out);
}

// round 9
// speedup vs baseline: 1.4193x; 1.0341x over previous
#include <cuda_runtime.h>
#include <cuda_bf16.h>
#include <math.h>
#include <stdint.h>

#define B_   2
#define T_   2048
#define D_   512
#define H_   8
#define DH_  64
#define M_   (B_*T_)   // 4096 token rows

// Scratch (no cudaMalloc allowed)
__device__ __nv_bfloat16 g_hb[M_*D_];        // LN output, bf16
__device__ __nv_bfloat16 g_wb[4*D_*D_];      // bf16 weights [k][n]: q,k,v,o
__device__ __nv_bfloat16 g_qb[M_*D_];        // q (pre-scaled by 1/8), bf16
__device__ __nv_bfloat16 g_kb[M_*D_];
__device__ __nv_bfloat16 g_vb[M_*D_];
__device__ __nv_bfloat16 g_ctxb[M_*D_];      // attention output, bf16

__device__ __forceinline__ uint32_t smem_u32(const void* p) {
    return (uint32_t)__cvta_generic_to_shared(p);
}

#define CP_ASYNC16(dst, src) \
    asm volatile("cp.async.cg.shared.global [%0], [%1], 16;" :: "r"(dst), "l"(src))
#define CP_COMMIT() asm volatile("cp.async.commit_group;")
#define CP_WAIT(n)  asm volatile("cp.async.wait_group %0;" :: "n"(n))

// ---------------------------------------------------------------------------
// 1) LayerNorm -> bf16 h : 128 threads/row, float4 loads
// ---------------------------------------------------------------------------
__global__ __launch_bounds__(128) void ln_kernel(const float* __restrict__ x,
                                                 const float* __restrict__ gamma,
                                                 const float* __restrict__ beta) {
    int row = blockIdx.x;
    int tid = threadIdx.x;
    const float4* xr = (const float4*)(x + (size_t)row * D_);
    float4 v = xr[tid];
    float s  = v.x + v.y + v.z + v.w;
    float s2 = v.x * v.x + v.y * v.y + v.z * v.z + v.w * v.w;
    #pragma unroll
    for (int o = 16; o > 0; o >>= 1) {
        s  += __shfl_xor_sync(0xFFFFFFFFu, s,  o);
        s2 += __shfl_xor_sync(0xFFFFFFFFu, s2, o);
    }
    __shared__ float rs[4], rs2[4];
    int wid = tid >> 5, lane = tid & 31;
    if (lane == 0) { rs[wid] = s; rs2[wid] = s2; }
    __syncthreads();
    s  = rs[0]  + rs[1]  + rs[2]  + rs[3];
    s2 = rs2[0] + rs2[1] + rs2[2] + rs2[3];
    float mean = s * (1.0f / D_);
    float var  = s2 * (1.0f / D_) - mean * mean;
    float rstd = rsqrtf(var + 1e-3f);
    float4 g = ((const float4*)gamma)[tid];
    float4 bb = ((const float4*)beta)[tid];
    float o0 = (v.x - mean) * rstd * g.x + bb.x;
    float o1 = (v.y - mean) * rstd * g.y + bb.y;
    float o2 = (v.z - mean) * rstd * g.z + bb.z;
    float o3 = (v.w - mean) * rstd * g.w + bb.w;
    __nv_bfloat162 p0 = __floats2bfloat162_rn(o0, o1);
    __nv_bfloat162 p1 = __floats2bfloat162_rn(o2, o3);
    uint2 pack = make_uint2(*(uint32_t*)&p0, *(uint32_t*)&p1);
    *(uint2*)(g_hb + (size_t)row * D_ + tid * 4) = pack;
}

// ---------------------------------------------------------------------------
// 1b) Weight conversion fp32 -> bf16
// ---------------------------------------------------------------------------
__global__ __launch_bounds__(256) void conv_kernel(const float* __restrict__ Wq,
                                                   const float* __restrict__ Wk,
                                                   const float* __restrict__ Wv,
                                                   const float* __restrict__ Wo) {
    size_t idx = ((size_t)blockIdx.x * 256 + threadIdx.x) * 4;
    int m = (int)(idx >> 18);
    size_t off = idx & ((1u << 18) - 1);
    const float* src;
    if (m == 0) src = Wq; else if (m == 1) src = Wk; else if (m == 2) src = Wv; else src = Wo;
    float4 v = *(const float4*)(src + off);
    __nv_bfloat162 lo = __floats2bfloat162_rn(v.x, v.y);
    __nv_bfloat162 hi = __floats2bfloat162_rn(v.z, v.w);
    *(__nv_bfloat162*)(g_wb + idx)     = lo;
    *(__nv_bfloat162*)(g_wb + idx + 2) = hi;
}

// ---------------------------------------------------------------------------
// bf16 MMA GEMM: BM=128, BN=128, BK=32; 2-stage cp.async, one sync/iter
// 8 warps in 4x2 grid, warp tile 32x64; m16n8k16
// ---------------------------------------------------------------------------
#define APAD 40    // 32+8 bf16
#define BPAD 136   // 128+8 bf16

__device__ __forceinline__ void mma16(float* c, const uint32_t* a, const uint32_t* b) {
    asm volatile(
        "mma.sync.aligned.m16n8k16.row.col.f32.bf16.bf16.f32 "
        "{%0,%1,%2,%3}, {%4,%5,%6,%7}, {%8,%9}, {%0,%1,%2,%3};"
        : "+f"(c[0]), "+f"(c[1]), "+f"(c[2]), "+f"(c[3])
        : "r"(a[0]), "r"(a[1]), "r"(a[2]), "r"(a[3]), "r"(b[0]), "r"(b[1]));
}

template <bool RESID, bool BF16OUT>
__device__ __forceinline__ void gemm_bf16(const __nv_bfloat16* __restrict__ A,
                                          const __nv_bfloat16* __restrict__ Bm,
                                          const float* __restrict__ bias,
                                          const float* __restrict__ resid,
                                          void* __restrict__ Cv,
                                          float scale,
                                          int bx, int by) {
    const int K = D_, N = D_;
    __shared__ __nv_bfloat16 As[2][128][APAD];
    __shared__ __nv_bfloat16 Bs[2][32][BPAD];

    int tid = threadIdx.x;
    int lane = tid & 31, wid = tid >> 5;
    int wm = wid & 3, wn = wid >> 2;      // 4x2 warp grid; warp tile 32(m) x 64(n)
    int m0 = by * 128, n0 = bx * 128;

    float acc[2][8][4];
    #pragma unroll
    for (int mt = 0; mt < 2; mt++)
        #pragma unroll
        for (int nt = 0; nt < 8; nt++)
            #pragma unroll
            for (int i = 0; i < 4; i++) acc[mt][nt][i] = 0.f;

    // A: 128x32 bf16 = 512 x 16B chunks -> 2/thread
    int ar = tid >> 2;            // 0..63 (rows ar, ar+64)
    int ac = (tid & 3) * 8;
    // B: 32x128 bf16 = 512 x 16B chunks -> 2/thread
    int br = tid >> 4;            // 0..15 (rows br, br+16)
    int bc = (tid & 15) * 8;

    uint32_t sA = smem_u32(&As[0][0][0]);
    uint32_t sB = smem_u32(&Bs[0][0][0]);
    const uint32_t ABUF = 128 * APAD * 2;
    const uint32_t BBUF = 32 * BPAD * 2;

    uint32_t dA0 = sA + (ar * APAD + ac) * 2;
    uint32_t dA1 = sA + ((ar + 64) * APAD + ac) * 2;
    uint32_t dB0 = sB + (br * BPAD + bc) * 2;
    uint32_t dB1 = sB + ((br + 16) * BPAD + bc) * 2;

    const __nv_bfloat16* gA0 = A + (size_t)(m0 + ar) * K + ac;
    const __nv_bfloat16* gA1 = A + (size_t)(m0 + ar + 64) * K + ac;
    const __nv_bfloat16* gB0 = Bm + (size_t)br * N + n0 + bc;
    const __nv_bfloat16* gB1 = Bm + (size_t)(br + 16) * N + n0 + bc;

    CP_ASYNC16(dA0, gA0);
    CP_ASYNC16(dA1, gA1);
    CP_ASYNC16(dB0, gB0);
    CP_ASYNC16(dB1, gB1);
    CP_COMMIT();

    const int NIT = K / 32;   // 16
    for (int it = 0; it < NIT; it++) {
        int buf = it & 1;
        CP_WAIT(0);
        __syncthreads();
        if (it + 1 < NIT) {
            int nb = (it + 1) & 1;
            int k0 = (it + 1) * 32;
            CP_ASYNC16(dA0 + nb * ABUF, gA0 + k0);
            CP_ASYNC16(dA1 + nb * ABUF, gA1 + k0);
            CP_ASYNC16(dB0 + nb * BBUF, gB0 + (size_t)k0 * N);
            CP_ASYNC16(dB1 + nb * BBUF, gB1 + (size_t)k0 * N);
            CP_COMMIT();
        }

        uint32_t aBase = sA + buf * ABUF;
        uint32_t bBase = sB + buf * BBUF;
        #pragma unroll
        for (int ks = 0; ks < 2; ks++) {
            int kq = ks * 16;
            uint32_t a[2][4], bf[4][4];
            #pragma unroll
            for (int mt = 0; mt < 2; mt++) {
                int row = wm * 32 + mt * 16 + (lane & 15);
                int col = kq + ((lane >> 4) * 8);
                uint32_t addr = aBase + (row * APAD + col) * 2;
                asm volatile("ldmatrix.sync.aligned.m8n8.x4.shared.b16 {%0,%1,%2,%3}, [%4];"
                             : "=r"(a[mt][0]), "=r"(a[mt][1]), "=r"(a[mt][2]), "=r"(a[mt][3])
                             : "r"(addr));
            }
            #pragma unroll
            for (int np = 0; np < 4; np++) {
                int row = kq + (lane & 15);
                int col = wn * 64 + np * 16 + ((lane >> 4) * 8);
                uint32_t addr = bBase + (row * BPAD + col) * 2;
                asm volatile("ldmatrix.sync.aligned.m8n8.x4.trans.shared.b16 {%0,%1,%2,%3}, [%4];"
                             : "=r"(bf[np][0]), "=r"(bf[np][1]), "=r"(bf[np][2]), "=r"(bf[np][3])
                             : "r"(addr));
            }
            #pragma unroll
            for (int mt = 0; mt < 2; mt++)
                #pragma unroll
                for (int nt = 0; nt < 8; nt++)
                    mma16(acc[mt][nt], a[mt], &bf[nt >> 1][(nt & 1) * 2]);
        }
    }

    #pragma unroll
    for (int mt = 0; mt < 2; mt++) {
        #pragma unroll
        for (int nt = 0; nt < 8; nt++) {
            int r0 = m0 + wm * 32 + mt * 16 + (lane >> 2);
            int c  = n0 + wn * 64 + nt * 8 + (lane & 3) * 2;
            float b0 = bias[c], b1 = bias[c + 1];
            float o00 = (acc[mt][nt][0] + b0) * scale;
            float o01 = (acc[mt][nt][1] + b1) * scale;
            float o10 = (acc[mt][nt][2] + b0) * scale;
            float o11 = (acc[mt][nt][3] + b1) * scale;
            if (BF16OUT) {
                __nv_bfloat16* C = (__nv_bfloat16*)Cv;
                *(__nv_bfloat162*)(C + (size_t)r0 * D_ + c)       = __floats2bfloat162_rn(o00, o01);
                *(__nv_bfloat162*)(C + (size_t)(r0 + 8) * D_ + c) = __floats2bfloat162_rn(o10, o11);
            } else {
                float* C = (float*)Cv;
                if (RESID) {
                    float2 r0v = *(const float2*)(resid + (size_t)r0 * D_ + c);
                    float2 r1v = *(const float2*)(resid + (size_t)(r0 + 8) * D_ + c);
                    o00 += r0v.x; o01 += r0v.y;
                    o10 += r1v.x; o11 += r1v.y;
                }
                *(float2*)(C + (size_t)r0 * D_ + c)       = make_float2(o00, o01);
                *(float2*)(C + (size_t)(r0 + 8) * D_ + c) = make_float2(o10, o11);
            }
        }
    }
}

__global__ __launch_bounds__(256) void qkv_kernel(const float* __restrict__ bq,
                                                  const float* __restrict__ bk,
                                                  const float* __restrict__ bv) {
    const float* bi; __nv_bfloat16* C; float scale;
    if (blockIdx.z == 0)      { bi = bq; C = g_qb; scale = 0.125f; }
    else if (blockIdx.z == 1) { bi = bk; C = g_kb; scale = 1.f; }
    else                      { bi = bv; C = g_vb; scale = 1.f; }
    const __nv_bfloat16* W = g_wb + (size_t)blockIdx.z * D_ * D_;
    gemm_bf16<false, true>(g_hb, W, bi, nullptr, C, scale, blockIdx.x, blockIdx.y);
}

__global__ __launch_bounds__(256) void out_kernel(const float* __restrict__ bo,
                                                  const float* __restrict__ x,
                                                  float* __restrict__ out) {
    gemm_bf16<true, false>(g_ctxb, g_wb + (size_t)3 * D_ * D_, bo, x, out, 1.f,
                           blockIdx.x, blockIdx.y);
}

// ---------------------------------------------------------------------------
// 3) Banded attention (R7 measured config, unchanged)
// ---------------------------------------------------------------------------
#define TQ 32
#define WROWS (TQ + 9)   // 41
#define KVPAD 68

__global__ __launch_bounds__(256) void attn_kernel() {
    __shared__ float Ks[WROWS][KVPAD];
    __shared__ float Vs[WROWS][KVPAD];

    int bh = blockIdx.y;
    int b = bh >> 3, h = bh & 7;
    int t0 = blockIdx.x * TQ;
    int tid = threadIdx.x;

    for (int idx = tid; idx < WROWS * 8; idx += 256) {
        int r = idx >> 3;
        int c = (idx & 7) * 8;
        int jg = t0 - 6 + r;
        if (jg >= 0 && jg < T_) {
            size_t base = ((size_t)(b * T_ + jg)) * D_ + h * DH_ + c;
            uint4 ku = *(const uint4*)(g_kb + base);
            uint4 vu = *(const uint4*)(g_vb + base);
            float2 k01 = __bfloat1622float2(*(__nv_bfloat162*)&ku.x);
            float2 k23 = __bfloat1622float2(*(__nv_bfloat162*)&ku.y);
            float2 k45 = __bfloat1622float2(*(__nv_bfloat162*)&ku.z);
            float2 k67 = __bfloat1622float2(*(__nv_bfloat162*)&ku.w);
            *(float4*)&Ks[r][c]     = make_float4(k01.x, k01.y, k23.x, k23.y);
            *(float4*)&Ks[r][c + 4] = make_float4(k45.x, k45.y, k67.x, k67.y);
            float2 v01 = __bfloat1622float2(*(__nv_bfloat162*)&vu.x);
            float2 v23 = __bfloat1622float2(*(__nv_bfloat162*)&vu.y);
            float2 v45 = __bfloat1622float2(*(__nv_bfloat162*)&vu.z);
            float2 v67 = __bfloat1622float2(*(__nv_bfloat162*)&vu.w);
            *(float4*)&Vs[r][c]     = make_float4(v01.x, v01.y, v23.x, v23.y);
            *(float4*)&Vs[r][c + 4] = make_float4(v45.x, v45.y, v67.x, v67.y);
        } else {
            float4 z = make_float4(0.f, 0.f, 0.f, 0.f);
            *(float4*)&Ks[r][c] = z; *(float4*)&Ks[r][c + 4] = z;
            *(float4*)&Vs[r][c] = z; *(float4*)&Vs[r][c + 4] = z;
        }
    }
    __syncthreads();

    int w = tid >> 5, lane = tid & 31;
    int sub = lane >> 3, di = lane & 7;
    int t = t0 + w * 4 + sub;
    int lo = max(t - 6, 0);
    int hi = min(t + 3, T_ - 1);
    int nw = hi - lo + 1;
    int rbase = lo - (t0 - 6);

    const __nv_bfloat16* qp = g_qb + ((size_t)(b * T_ + t)) * D_ + h * DH_ + di * 8;
    uint4 qu = *(const uint4*)qp;
    float2 q01 = __bfloat1622float2(*(__nv_bfloat162*)&qu.x);
    float2 q23 = __bfloat1622float2(*(__nv_bfloat162*)&qu.y);
    float2 q45 = __bfloat1622float2(*(__nv_bfloat162*)&qu.z);
    float2 q67 = __bfloat1622float2(*(__nv_bfloat162*)&qu.w);

    float sc[10];
    float mx = -1e30f;
    #pragma unroll
    for (int jj = 0; jj < 10; jj++) {
        int r = rbase + jj;
        const float* kr = &Ks[r][di * 8];
        float4 k0 = *(const float4*)kr;
        float4 k1 = *(const float4*)(kr + 4);
        float s = q01.x * k0.x + q01.y * k0.y + q23.x * k0.z + q23.y * k0.w
                + q45.x * k1.x + q45.y * k1.y + q67.x * k1.z + q67.y * k1.w;
        s += __shfl_xor_sync(0xFFFFFFFFu, s, 4);
        s += __shfl_xor_sync(0xFFFFFFFFu, s, 2);
        s += __shfl_xor_sync(0xFFFFFFFFu, s, 1);
        s = (jj < nw) ? s : -1e30f;
        sc[jj] = s;
        mx = fmaxf(mx, s);
    }

    float denom = 0.f;
    float a0 = 0.f, a1 = 0.f, a2 = 0.f, a3 = 0.f;
    float a4 = 0.f, a5 = 0.f, a6 = 0.f, a7 = 0.f;
    #pragma unroll
    for (int jj = 0; jj < 10; jj++) {
        float p = __expf(sc[jj] - mx);
        denom += p;
        int r = rbase + jj;
        const float* vr = &Vs[r][di * 8];
        float4 v0 = *(const float4*)vr;
        float4 v1 = *(const float4*)(vr + 4);
        a0 = fmaf(p, v0.x, a0); a1 = fmaf(p, v0.y, a1);
        a2 = fmaf(p, v0.z, a2); a3 = fmaf(p, v0.w, a3);
        a4 = fmaf(p, v1.x, a4); a5 = fmaf(p, v1.y, a5);
        a6 = fmaf(p, v1.z, a6); a7 = fmaf(p, v1.w, a7);
    }
    float inv = 1.f / denom;

    __nv_bfloat162 o0 = __floats2bfloat162_rn(a0 * inv, a1 * inv);
    __nv_bfloat162 o1 = __floats2bfloat162_rn(a2 * inv, a3 * inv);
    __nv_bfloat162 o2 = __floats2bfloat162_rn(a4 * inv, a5 * inv);
    __nv_bfloat162 o3 = __floats2bfloat162_rn(a6 * inv, a7 * inv);
    uint4 pack;
    pack.x = *(uint32_t*)&o0; pack.y = *(uint32_t*)&o1;
    pack.z = *(uint32_t*)&o2; pack.w = *(uint32_t*)&o3;
    *(uint4*)(g_ctxb + ((size_t)(b * T_ + t)) * D_ + h * DH_ + di * 8) = pack;
}

// ---------------------------------------------------------------------------
// Launch
// ---------------------------------------------------------------------------
extern "C" void kernel_launch(void* const* d_in, const int* in_sizes, int n_in,
                              void* d_out, int out_size) {
    const float* x     = (const float*)d_in[0];
    const float* gamma = (const float*)d_in[1];
    const float* beta  = (const float*)d_in[2];
    const float* Wq    = (const float*)d_in[3];
    const float* bq    = (const float*)d_in[4];
    const float* Wk    = (const float*)d_in[5];
    const float* bk    = (const float*)d_in[6];
    const float* Wv    = (const float*)d_in[7];
    const float* bv    = (const float*)d_in[8];
    const float* Wo    = (const float*)d_in[9];
    const float* bo    = (const float*)d_in[10];
    float* out = (float*)d_out;

    conv_kernel<<<(4 * D_ * D_) / (256 * 4), 256>>>(Wq, Wk, Wv, Wo);
    ln_kernel<<<M_, 128>>>(x, gamma, beta);
    qkv_kernel<<<dim3(D_/128, M_/128, 3), 256>>>(bq, bk, bv);
    attn_kernel<<<dim3(T_/TQ, B_*H_), 256>>>();
    out_kernel<<<dim3(D_/128, M_/128), 256>>>(bo, x, out);
}

// round 10
// speedup vs baseline: 1.5669x; 1.1040x over previous
#include <cuda_runtime.h>
#include <cuda_bf16.h>
#include <math.h>
#include <stdint.h>

#define B_   2
#define T_   2048
#define D_   512
#define H_   8
#define DH_  64
#define M_   (B_*T_)   // 4096 token rows

// Scratch (no cudaMalloc allowed)
__device__ __nv_bfloat16 g_hb[M_*D_];        // LN output, bf16
__device__ __nv_bfloat16 g_wb[4*D_*D_];      // bf16 weights [k][n]: q,k,v,o
__device__ __nv_bfloat16 g_qb[M_*D_];        // q (pre-scaled by 1/8), bf16
__device__ __nv_bfloat16 g_kb[M_*D_];
__device__ __nv_bfloat16 g_vb[M_*D_];
__device__ __nv_bfloat16 g_ctxb[M_*D_];      // attention output, bf16

__device__ __forceinline__ uint32_t smem_u32(const void* p) {
    return (uint32_t)__cvta_generic_to_shared(p);
}

#define CP_ASYNC16(dst, src) \
    asm volatile("cp.async.cg.shared.global [%0], [%1], 16;" :: "r"(dst), "l"(src))
#define CP_COMMIT() asm volatile("cp.async.commit_group;")
#define CP_WAIT(n)  asm volatile("cp.async.wait_group %0;" :: "n"(n))

// ---------------------------------------------------------------------------
// 1) Fused pre-kernel: blocks [0,4096) = LayerNorm rows (128 thr/row);
//    blocks [4096,6144) = weight fp32->bf16 conversion (512 elems/block)
// ---------------------------------------------------------------------------
__global__ __launch_bounds__(128) void pre_kernel(const float* __restrict__ x,
                                                  const float* __restrict__ gamma,
                                                  const float* __restrict__ beta,
                                                  const float* __restrict__ Wq,
                                                  const float* __restrict__ Wk,
                                                  const float* __restrict__ Wv,
                                                  const float* __restrict__ Wo) {
    int tid = threadIdx.x;
    if (blockIdx.x >= M_) {
        // weight conversion: 2048 blocks x 128 threads x 4 floats
        size_t idx = ((size_t)(blockIdx.x - M_) * 128 + tid) * 4;
        int m = (int)(idx >> 18);
        size_t off = idx & ((1u << 18) - 1);
        const float* src;
        if (m == 0) src = Wq; else if (m == 1) src = Wk;
        else if (m == 2) src = Wv; else src = Wo;
        float4 v = *(const float4*)(src + off);
        __nv_bfloat162 lo = __floats2bfloat162_rn(v.x, v.y);
        __nv_bfloat162 hi = __floats2bfloat162_rn(v.z, v.w);
        *(__nv_bfloat162*)(g_wb + idx)     = lo;
        *(__nv_bfloat162*)(g_wb + idx + 2) = hi;
        return;
    }
    int row = blockIdx.x;
    const float4* xr = (const float4*)(x + (size_t)row * D_);
    float4 v = xr[tid];
    float s  = v.x + v.y + v.z + v.w;
    float s2 = v.x * v.x + v.y * v.y + v.z * v.z + v.w * v.w;
    #pragma unroll
    for (int o = 16; o > 0; o >>= 1) {
        s  += __shfl_xor_sync(0xFFFFFFFFu, s,  o);
        s2 += __shfl_xor_sync(0xFFFFFFFFu, s2, o);
    }
    __shared__ float rs[4], rs2[4];
    int wid = tid >> 5, lane = tid & 31;
    if (lane == 0) { rs[wid] = s; rs2[wid] = s2; }
    __syncthreads();
    s  = rs[0]  + rs[1]  + rs[2]  + rs[3];
    s2 = rs2[0] + rs2[1] + rs2[2] + rs2[3];
    float mean = s * (1.0f / D_);
    float var  = s2 * (1.0f / D_) - mean * mean;
    float rstd = rsqrtf(var + 1e-3f);
    float4 g = ((const float4*)gamma)[tid];
    float4 bb = ((const float4*)beta)[tid];
    float o0 = (v.x - mean) * rstd * g.x + bb.x;
    float o1 = (v.y - mean) * rstd * g.y + bb.y;
    float o2 = (v.z - mean) * rstd * g.z + bb.z;
    float o3 = (v.w - mean) * rstd * g.w + bb.w;
    __nv_bfloat162 p0 = __floats2bfloat162_rn(o0, o1);
    __nv_bfloat162 p1 = __floats2bfloat162_rn(o2, o3);
    uint2 pack = make_uint2(*(uint32_t*)&p0, *(uint32_t*)&p1);
    *(uint2*)(g_hb + (size_t)row * D_ + tid * 4) = pack;
}

// ---------------------------------------------------------------------------
// bf16 MMA GEMM: BM=128, BN=128, BK=32; 2-stage cp.async, one sync/iter
// ---------------------------------------------------------------------------
#define APAD 40    // 32+8 bf16
#define BPAD 136   // 128+8 bf16

__device__ __forceinline__ void mma16(float* c, const uint32_t* a, const uint32_t* b) {
    asm volatile(
        "mma.sync.aligned.m16n8k16.row.col.f32.bf16.bf16.f32 "
        "{%0,%1,%2,%3}, {%4,%5,%6,%7}, {%8,%9}, {%0,%1,%2,%3};"
        : "+f"(c[0]), "+f"(c[1]), "+f"(c[2]), "+f"(c[3])
        : "r"(a[0]), "r"(a[1]), "r"(a[2]), "r"(a[3]), "r"(b[0]), "r"(b[1]));
}

template <bool RESID, bool BF16OUT>
__device__ __forceinline__ void gemm_bf16(const __nv_bfloat16* __restrict__ A,
                                          const __nv_bfloat16* __restrict__ Bm,
                                          const float* __restrict__ bias,
                                          const float* __restrict__ resid,
                                          void* __restrict__ Cv,
                                          float scale,
                                          int bx, int by) {
    const int K = D_, N = D_;
    __shared__ __nv_bfloat16 As[2][128][APAD];
    __shared__ __nv_bfloat16 Bs[2][32][BPAD];

    int tid = threadIdx.x;
    int lane = tid & 31, wid = tid >> 5;
    int wm = wid & 3, wn = wid >> 2;
    int m0 = by * 128, n0 = bx * 128;

    float acc[2][8][4];
    #pragma unroll
    for (int mt = 0; mt < 2; mt++)
        #pragma unroll
        for (int nt = 0; nt < 8; nt++)
            #pragma unroll
            for (int i = 0; i < 4; i++) acc[mt][nt][i] = 0.f;

    int ar = tid >> 2;
    int ac = (tid & 3) * 8;
    int br = tid >> 4;
    int bc = (tid & 15) * 8;

    uint32_t sA = smem_u32(&As[0][0][0]);
    uint32_t sB = smem_u32(&Bs[0][0][0]);
    const uint32_t ABUF = 128 * APAD * 2;
    const uint32_t BBUF = 32 * BPAD * 2;

    uint32_t dA0 = sA + (ar * APAD + ac) * 2;
    uint32_t dA1 = sA + ((ar + 64) * APAD + ac) * 2;
    uint32_t dB0 = sB + (br * BPAD + bc) * 2;
    uint32_t dB1 = sB + ((br + 16) * BPAD + bc) * 2;

    const __nv_bfloat16* gA0 = A + (size_t)(m0 + ar) * K + ac;
    const __nv_bfloat16* gA1 = A + (size_t)(m0 + ar + 64) * K + ac;
    const __nv_bfloat16* gB0 = Bm + (size_t)br * N + n0 + bc;
    const __nv_bfloat16* gB1 = Bm + (size_t)(br + 16) * N + n0 + bc;

    CP_ASYNC16(dA0, gA0);
    CP_ASYNC16(dA1, gA1);
    CP_ASYNC16(dB0, gB0);
    CP_ASYNC16(dB1, gB1);
    CP_COMMIT();

    const int NIT = K / 32;   // 16
    for (int it = 0; it < NIT; it++) {
        int buf = it & 1;
        CP_WAIT(0);
        __syncthreads();
        if (it + 1 < NIT) {
            int nb = (it + 1) & 1;
            int k0 = (it + 1) * 32;
            CP_ASYNC16(dA0 + nb * ABUF, gA0 + k0);
            CP_ASYNC16(dA1 + nb * ABUF, gA1 + k0);
            CP_ASYNC16(dB0 + nb * BBUF, gB0 + (size_t)k0 * N);
            CP_ASYNC16(dB1 + nb * BBUF, gB1 + (size_t)k0 * N);
            CP_COMMIT();
        }

        uint32_t aBase = sA + buf * ABUF;
        uint32_t bBase = sB + buf * BBUF;
        #pragma unroll
        for (int ks = 0; ks < 2; ks++) {
            int kq = ks * 16;
            uint32_t a[2][4], bf[4][4];
            #pragma unroll
            for (int mt = 0; mt < 2; mt++) {
                int row = wm * 32 + mt * 16 + (lane & 15);
                int col = kq + ((lane >> 4) * 8);
                uint32_t addr = aBase + (row * APAD + col) * 2;
                asm volatile("ldmatrix.sync.aligned.m8n8.x4.shared.b16 {%0,%1,%2,%3}, [%4];"
                             : "=r"(a[mt][0]), "=r"(a[mt][1]), "=r"(a[mt][2]), "=r"(a[mt][3])
                             : "r"(addr));
            }
            #pragma unroll
            for (int np = 0; np < 4; np++) {
                int row = kq + (lane & 15);
                int col = wn * 64 + np * 16 + ((lane >> 4) * 8);
                uint32_t addr = bBase + (row * BPAD + col) * 2;
                asm volatile("ldmatrix.sync.aligned.m8n8.x4.trans.shared.b16 {%0,%1,%2,%3}, [%4];"
                             : "=r"(bf[np][0]), "=r"(bf[np][1]), "=r"(bf[np][2]), "=r"(bf[np][3])
                             : "r"(addr));
            }
            #pragma unroll
            for (int mt = 0; mt < 2; mt++)
                #pragma unroll
                for (int nt = 0; nt < 8; nt++)
                    mma16(acc[mt][nt], a[mt], &bf[nt >> 1][(nt & 1) * 2]);
        }
    }

    #pragma unroll
    for (int mt = 0; mt < 2; mt++) {
        #pragma unroll
        for (int nt = 0; nt < 8; nt++) {
            int r0 = m0 + wm * 32 + mt * 16 + (lane >> 2);
            int c  = n0 + wn * 64 + nt * 8 + (lane & 3) * 2;
            float b0 = bias[c], b1 = bias[c + 1];
            float o00 = (acc[mt][nt][0] + b0) * scale;
            float o01 = (acc[mt][nt][1] + b1) * scale;
            float o10 = (acc[mt][nt][2] + b0) * scale;
            float o11 = (acc[mt][nt][3] + b1) * scale;
            if (BF16OUT) {
                __nv_bfloat16* C = (__nv_bfloat16*)Cv;
                *(__nv_bfloat162*)(C + (size_t)r0 * D_ + c)       = __floats2bfloat162_rn(o00, o01);
                *(__nv_bfloat162*)(C + (size_t)(r0 + 8) * D_ + c) = __floats2bfloat162_rn(o10, o11);
            } else {
                float* C = (float*)Cv;
                if (RESID) {
                    float2 r0v = *(const float2*)(resid + (size_t)r0 * D_ + c);
                    float2 r1v = *(const float2*)(resid + (size_t)(r0 + 8) * D_ + c);
                    o00 += r0v.x; o01 += r0v.y;
                    o10 += r1v.x; o11 += r1v.y;
                }
                *(float2*)(C + (size_t)r0 * D_ + c)       = make_float2(o00, o01);
                *(float2*)(C + (size_t)(r0 + 8) * D_ + c) = make_float2(o10, o11);
            }
        }
    }
}

__global__ __launch_bounds__(256) void qkv_kernel(const float* __restrict__ bq,
                                                  const float* __restrict__ bk,
                                                  const float* __restrict__ bv) {
    const float* bi; __nv_bfloat16* C; float scale;
    if (blockIdx.z == 0)      { bi = bq; C = g_qb; scale = 0.125f; }
    else if (blockIdx.z == 1) { bi = bk; C = g_kb; scale = 1.f; }
    else                      { bi = bv; C = g_vb; scale = 1.f; }
    const __nv_bfloat16* W = g_wb + (size_t)blockIdx.z * D_ * D_;
    gemm_bf16<false, true>(g_hb, W, bi, nullptr, C, scale, blockIdx.x, blockIdx.y);
}

__global__ __launch_bounds__(256) void out_kernel(const float* __restrict__ bo,
                                                  const float* __restrict__ x,
                                                  float* __restrict__ out) {
    gemm_bf16<true, false>(g_ctxb, g_wb + (size_t)3 * D_ * D_, bo, x, out, 1.f,
                           blockIdx.x, blockIdx.y);
}

// ---------------------------------------------------------------------------
// 3) Banded attention: conflict-free lane->dim map.
//    Lane di owns dims {di*4..di*4+3, 32+di*4..32+di*4+3}: each 8-lane LDS
//    phase covers words r*68 + {0,4,...,28}(+32) -> all 32 banks distinct.
// ---------------------------------------------------------------------------
#define TQ 32
#define WROWS (TQ + 9)   // 41
#define KVPAD 68

__global__ __launch_bounds__(256) void attn_kernel() {
    __shared__ float Ks[WROWS][KVPAD];
    __shared__ float Vs[WROWS][KVPAD];

    int bh = blockIdx.y;
    int b = bh >> 3, h = bh & 7;
    int t0 = blockIdx.x * TQ;
    int tid = threadIdx.x;

    for (int idx = tid; idx < WROWS * 8; idx += 256) {
        int r = idx >> 3;
        int c = (idx & 7) * 8;
        int jg = t0 - 6 + r;
        if (jg >= 0 && jg < T_) {
            size_t base = ((size_t)(b * T_ + jg)) * D_ + h * DH_ + c;
            uint4 ku = *(const uint4*)(g_kb + base);
            uint4 vu = *(const uint4*)(g_vb + base);
            float2 k01 = __bfloat1622float2(*(__nv_bfloat162*)&ku.x);
            float2 k23 = __bfloat1622float2(*(__nv_bfloat162*)&ku.y);
            float2 k45 = __bfloat1622float2(*(__nv_bfloat162*)&ku.z);
            float2 k67 = __bfloat1622float2(*(__nv_bfloat162*)&ku.w);
            *(float4*)&Ks[r][c]     = make_float4(k01.x, k01.y, k23.x, k23.y);
            *(float4*)&Ks[r][c + 4] = make_float4(k45.x, k45.y, k67.x, k67.y);
            float2 v01 = __bfloat1622float2(*(__nv_bfloat162*)&vu.x);
            float2 v23 = __bfloat1622float2(*(__nv_bfloat162*)&vu.y);
            float2 v45 = __bfloat1622float2(*(__nv_bfloat162*)&vu.z);
            float2 v67 = __bfloat1622float2(*(__nv_bfloat162*)&vu.w);
            *(float4*)&Vs[r][c]     = make_float4(v01.x, v01.y, v23.x, v23.y);
            *(float4*)&Vs[r][c + 4] = make_float4(v45.x, v45.y, v67.x, v67.y);
        } else {
            float4 z = make_float4(0.f, 0.f, 0.f, 0.f);
            *(float4*)&Ks[r][c] = z; *(float4*)&Ks[r][c + 4] = z;
            *(float4*)&Vs[r][c] = z; *(float4*)&Vs[r][c + 4] = z;
        }
    }
    __syncthreads();

    int w = tid >> 5, lane = tid & 31;
    int sub = lane >> 3, di = lane & 7;
    int t = t0 + w * 4 + sub;
    int lo = max(t - 6, 0);
    int hi = min(t + 3, T_ - 1);
    int nw = hi - lo + 1;
    int rbase = lo - (t0 - 6);

    // q: lane owns dims di*4..+3 and 32+di*4..+3 (pre-scaled by 1/8)
    const __nv_bfloat16* qp = g_qb + ((size_t)(b * T_ + t)) * D_ + h * DH_ + di * 4;
    uint2 qa = *(const uint2*)qp;
    uint2 qbv = *(const uint2*)(qp + 32);
    float2 q01 = __bfloat1622float2(*(__nv_bfloat162*)&qa.x);
    float2 q23 = __bfloat1622float2(*(__nv_bfloat162*)&qa.y);
    float2 q45 = __bfloat1622float2(*(__nv_bfloat162*)&qbv.x);
    float2 q67 = __bfloat1622float2(*(__nv_bfloat162*)&qbv.y);

    float sc[10];
    float mx = -1e30f;
    #pragma unroll
    for (int jj = 0; jj < 10; jj++) {
        int r = rbase + jj;
        float4 k0 = *(const float4*)&Ks[r][di * 4];
        float4 k1 = *(const float4*)&Ks[r][32 + di * 4];
        float s = q01.x * k0.x + q01.y * k0.y + q23.x * k0.z + q23.y * k0.w
                + q45.x * k1.x + q45.y * k1.y + q67.x * k1.z + q67.y * k1.w;
        s += __shfl_xor_sync(0xFFFFFFFFu, s, 4);
        s += __shfl_xor_sync(0xFFFFFFFFu, s, 2);
        s += __shfl_xor_sync(0xFFFFFFFFu, s, 1);
        s = (jj < nw) ? s : -1e30f;
        sc[jj] = s;
        mx = fmaxf(mx, s);
    }

    float denom = 0.f;
    float a0 = 0.f, a1 = 0.f, a2 = 0.f, a3 = 0.f;
    float a4 = 0.f, a5 = 0.f, a6 = 0.f, a7 = 0.f;
    #pragma unroll
    for (int jj = 0; jj < 10; jj++) {
        float p = __expf(sc[jj] - mx);
        denom += p;
        int r = rbase + jj;
        float4 v0 = *(const float4*)&Vs[r][di * 4];
        float4 v1 = *(const float4*)&Vs[r][32 + di * 4];
        a0 = fmaf(p, v0.x, a0); a1 = fmaf(p, v0.y, a1);
        a2 = fmaf(p, v0.z, a2); a3 = fmaf(p, v0.w, a3);
        a4 = fmaf(p, v1.x, a4); a5 = fmaf(p, v1.y, a5);
        a6 = fmaf(p, v1.z, a6); a7 = fmaf(p, v1.w, a7);
    }
    float inv = 1.f / denom;

    __nv_bfloat162 o0 = __floats2bfloat162_rn(a0 * inv, a1 * inv);
    __nv_bfloat162 o1 = __floats2bfloat162_rn(a2 * inv, a3 * inv);
    __nv_bfloat162 o2 = __floats2bfloat162_rn(a4 * inv, a5 * inv);
    __nv_bfloat162 o3 = __floats2bfloat162_rn(a6 * inv, a7 * inv);
    __nv_bfloat16* cp = g_ctxb + ((size_t)(b * T_ + t)) * D_ + h * DH_ + di * 4;
    *(uint2*)cp        = make_uint2(*(uint32_t*)&o0, *(uint32_t*)&o1);
    *(uint2*)(cp + 32) = make_uint2(*(uint32_t*)&o2, *(uint32_t*)&o3);
}

// ---------------------------------------------------------------------------
// Launch
// ---------------------------------------------------------------------------
extern "C" void kernel_launch(void* const* d_in, const int* in_sizes, int n_in,
                              void* d_out, int out_size) {
    const float* x     = (const float*)d_in[0];
    const float* gamma = (const float*)d_in[1];
    const float* beta  = (const float*)d_in[2];
    const float* Wq    = (const float*)d_in[3];
    const float* bq    = (const float*)d_in[4];
    const float* Wk    = (const float*)d_in[5];
    const float* bk    = (const float*)d_in[6];
    const float* Wv    = (const float*)d_in[7];
    const float* bv    = (const float*)d_in[8];
    const float* Wo    = (const float*)d_in[9];
    const float* bo    = (const float*)d_in[10];
    float* out = (float*)d_out;

    pre_kernel<<<M_ + 2048, 128>>>(x, gamma, beta, Wq, Wk, Wv, Wo);
    qkv_kernel<<<dim3(D_/128, M_/128, 3), 256>>>(bq, bk, bv);
    attn_kernel<<<dim3(T_/TQ, B_*H_), 256>>>();
    out_kernel<<<dim3(D_/128, M_/128), 256>>>(bo, x, out);
}

// round 11
// speedup vs baseline: 1.5721x; 1.0033x over previous
#include <cuda_runtime.h>
#include <cuda_bf16.h>
#include <math.h>
#include <stdint.h>

#define B_   2
#define T_   2048
#define D_   512
#define H_   8
#define DH_  64
#define M_   (B_*T_)   // 4096 token rows

// Scratch (no cudaMalloc allowed)
__device__ __nv_bfloat16 g_hb[M_*D_];        // LN output, bf16
__device__ __nv_bfloat16 g_wb[4*D_*D_];      // bf16 weights [k][n]: q,k,v,o
__device__ __nv_bfloat16 g_qb[M_*D_];        // q (pre-scaled by 1/8), bf16
__device__ __nv_bfloat16 g_kb[M_*D_];
__device__ __nv_bfloat16 g_vb[M_*D_];
__device__ __nv_bfloat16 g_ctxb[M_*D_];      // attention output, bf16

__device__ __forceinline__ uint32_t smem_u32(const void* p) {
    return (uint32_t)__cvta_generic_to_shared(p);
}

#define CP_ASYNC16(dst, src) \
    asm volatile("cp.async.cg.shared.global [%0], [%1], 16;" :: "r"(dst), "l"(src))
#define CP_COMMIT() asm volatile("cp.async.commit_group;")
#define CP_WAIT(n)  asm volatile("cp.async.wait_group %0;" :: "n"(n))

// ---------------------------------------------------------------------------
// 1) Fused pre-kernel: blocks [0,4096) = LayerNorm rows (128 thr/row);
//    blocks [4096,6144) = weight fp32->bf16 conversion
// ---------------------------------------------------------------------------
__global__ __launch_bounds__(128) void pre_kernel(const float* __restrict__ x,
                                                  const float* __restrict__ gamma,
                                                  const float* __restrict__ beta,
                                                  const float* __restrict__ Wq,
                                                  const float* __restrict__ Wk,
                                                  const float* __restrict__ Wv,
                                                  const float* __restrict__ Wo) {
    int tid = threadIdx.x;
    if (blockIdx.x >= M_) {
        size_t idx = ((size_t)(blockIdx.x - M_) * 128 + tid) * 4;
        int m = (int)(idx >> 18);
        size_t off = idx & ((1u << 18) - 1);
        const float* src;
        if (m == 0) src = Wq; else if (m == 1) src = Wk;
        else if (m == 2) src = Wv; else src = Wo;
        float4 v = *(const float4*)(src + off);
        __nv_bfloat162 lo = __floats2bfloat162_rn(v.x, v.y);
        __nv_bfloat162 hi = __floats2bfloat162_rn(v.z, v.w);
        *(__nv_bfloat162*)(g_wb + idx)     = lo;
        *(__nv_bfloat162*)(g_wb + idx + 2) = hi;
        return;
    }
    int row = blockIdx.x;
    const float4* xr = (const float4*)(x + (size_t)row * D_);
    float4 v = xr[tid];
    float s  = v.x + v.y + v.z + v.w;
    float s2 = v.x * v.x + v.y * v.y + v.z * v.z + v.w * v.w;
    #pragma unroll
    for (int o = 16; o > 0; o >>= 1) {
        s  += __shfl_xor_sync(0xFFFFFFFFu, s,  o);
        s2 += __shfl_xor_sync(0xFFFFFFFFu, s2, o);
    }
    __shared__ float rs[4], rs2[4];
    int wid = tid >> 5, lane = tid & 31;
    if (lane == 0) { rs[wid] = s; rs2[wid] = s2; }
    __syncthreads();
    s  = rs[0]  + rs[1]  + rs[2]  + rs[3];
    s2 = rs2[0] + rs2[1] + rs2[2] + rs2[3];
    float mean = s * (1.0f / D_);
    float var  = s2 * (1.0f / D_) - mean * mean;
    float rstd = rsqrtf(var + 1e-3f);
    float4 g = ((const float4*)gamma)[tid];
    float4 bb = ((const float4*)beta)[tid];
    float o0 = (v.x - mean) * rstd * g.x + bb.x;
    float o1 = (v.y - mean) * rstd * g.y + bb.y;
    float o2 = (v.z - mean) * rstd * g.z + bb.z;
    float o3 = (v.w - mean) * rstd * g.w + bb.w;
    __nv_bfloat162 p0 = __floats2bfloat162_rn(o0, o1);
    __nv_bfloat162 p1 = __floats2bfloat162_rn(o2, o3);
    uint2 pack = make_uint2(*(uint32_t*)&p0, *(uint32_t*)&p1);
    *(uint2*)(g_hb + (size_t)row * D_ + tid * 4) = pack;
}

// ---------------------------------------------------------------------------
// bf16 MMA GEMM, BN templated: BM=128, BN in {64,128}, BK=32
// 8 warps 4x2; warp tile 32 x (BN/2); 2-stage cp.async, one sync/iter
// ---------------------------------------------------------------------------
#define APAD 40    // 32+8 bf16

__device__ __forceinline__ void mma16(float* c, const uint32_t* a, const uint32_t* b) {
    asm volatile(
        "mma.sync.aligned.m16n8k16.row.col.f32.bf16.bf16.f32 "
        "{%0,%1,%2,%3}, {%4,%5,%6,%7}, {%8,%9}, {%0,%1,%2,%3};"
        : "+f"(c[0]), "+f"(c[1]), "+f"(c[2]), "+f"(c[3])
        : "r"(a[0]), "r"(a[1]), "r"(a[2]), "r"(a[3]), "r"(b[0]), "r"(b[1]));
}

template <int BNN, bool RESID, bool BF16OUT>
__device__ __forceinline__ void gemm_bf16(const __nv_bfloat16* __restrict__ A,
                                          const __nv_bfloat16* __restrict__ Bm,
                                          const float* __restrict__ bias,
                                          const float* __restrict__ resid,
                                          void* __restrict__ Cv,
                                          float scale,
                                          int bx, int by) {
    const int K = D_, N = D_;
    constexpr int BPADN = BNN + 8;
    constexpr int WN = BNN / 2;       // warp n-extent
    constexpr int NT = BNN / 16;      // n-tiles of 8 per warp
    constexpr int NP = BNN / 32;      // ldmatrix x4 groups per warp
    __shared__ __nv_bfloat16 As[2][128][APAD];
    __shared__ __nv_bfloat16 Bs[2][32][BPADN];

    int tid = threadIdx.x;
    int lane = tid & 31, wid = tid >> 5;
    int wm = wid & 3, wn = wid >> 2;
    int m0 = by * 128, n0 = bx * BNN;

    float acc[2][NT][4];
    #pragma unroll
    for (int mt = 0; mt < 2; mt++)
        #pragma unroll
        for (int nt = 0; nt < NT; nt++)
            #pragma unroll
            for (int i = 0; i < 4; i++) acc[mt][nt][i] = 0.f;

    int ar = tid >> 2;
    int ac = (tid & 3) * 8;
    int br, bc;
    if (BNN == 128) { br = tid >> 4; bc = (tid & 15) * 8; }
    else            { br = tid >> 3; bc = (tid & 7) * 8; }

    uint32_t sA = smem_u32(&As[0][0][0]);
    uint32_t sB = smem_u32(&Bs[0][0][0]);
    const uint32_t ABUF = 128 * APAD * 2;
    const uint32_t BBUF = 32 * BPADN * 2;

    uint32_t dA0 = sA + (ar * APAD + ac) * 2;
    uint32_t dA1 = sA + ((ar + 64) * APAD + ac) * 2;
    uint32_t dB0 = sB + (br * BPADN + bc) * 2;
    uint32_t dB1 = sB + ((br + 16) * BPADN + bc) * 2;   // used only when BNN==128

    const __nv_bfloat16* gA0 = A + (size_t)(m0 + ar) * K + ac;
    const __nv_bfloat16* gA1 = A + (size_t)(m0 + ar + 64) * K + ac;
    const __nv_bfloat16* gB0 = Bm + (size_t)br * N + n0 + bc;
    const __nv_bfloat16* gB1 = Bm + (size_t)(br + 16) * N + n0 + bc;

    CP_ASYNC16(dA0, gA0);
    CP_ASYNC16(dA1, gA1);
    CP_ASYNC16(dB0, gB0);
    if (BNN == 128) CP_ASYNC16(dB1, gB1);
    CP_COMMIT();

    const int NIT = K / 32;   // 16
    for (int it = 0; it < NIT; it++) {
        int buf = it & 1;
        CP_WAIT(0);
        __syncthreads();
        if (it + 1 < NIT) {
            int nb = (it + 1) & 1;
            int k0 = (it + 1) * 32;
            CP_ASYNC16(dA0 + nb * ABUF, gA0 + k0);
            CP_ASYNC16(dA1 + nb * ABUF, gA1 + k0);
            CP_ASYNC16(dB0 + nb * BBUF, gB0 + (size_t)k0 * N);
            if (BNN == 128) CP_ASYNC16(dB1 + nb * BBUF, gB1 + (size_t)k0 * N);
            CP_COMMIT();
        }

        uint32_t aBase = sA + buf * ABUF;
        uint32_t bBase = sB + buf * BBUF;
        #pragma unroll
        for (int ks = 0; ks < 2; ks++) {
            int kq = ks * 16;
            uint32_t a[2][4], bf[NP][4];
            #pragma unroll
            for (int mt = 0; mt < 2; mt++) {
                int row = wm * 32 + mt * 16 + (lane & 15);
                int col = kq + ((lane >> 4) * 8);
                uint32_t addr = aBase + (row * APAD + col) * 2;
                asm volatile("ldmatrix.sync.aligned.m8n8.x4.shared.b16 {%0,%1,%2,%3}, [%4];"
                             : "=r"(a[mt][0]), "=r"(a[mt][1]), "=r"(a[mt][2]), "=r"(a[mt][3])
                             : "r"(addr));
            }
            #pragma unroll
            for (int np = 0; np < NP; np++) {
                int row = kq + (lane & 15);
                int col = wn * WN + np * 16 + ((lane >> 4) * 8);
                uint32_t addr = bBase + (row * BPADN + col) * 2;
                asm volatile("ldmatrix.sync.aligned.m8n8.x4.trans.shared.b16 {%0,%1,%2,%3}, [%4];"
                             : "=r"(bf[np][0]), "=r"(bf[np][1]), "=r"(bf[np][2]), "=r"(bf[np][3])
                             : "r"(addr));
            }
            #pragma unroll
            for (int mt = 0; mt < 2; mt++)
                #pragma unroll
                for (int nt = 0; nt < NT; nt++)
                    mma16(acc[mt][nt], a[mt], &bf[nt >> 1][(nt & 1) * 2]);
        }
    }

    #pragma unroll
    for (int mt = 0; mt < 2; mt++) {
        #pragma unroll
        for (int nt = 0; nt < NT; nt++) {
            int r0 = m0 + wm * 32 + mt * 16 + (lane >> 2);
            int c  = n0 + wn * WN + nt * 8 + (lane & 3) * 2;
            float b0 = bias[c], b1 = bias[c + 1];
            float o00 = (acc[mt][nt][0] + b0) * scale;
            float o01 = (acc[mt][nt][1] + b1) * scale;
            float o10 = (acc[mt][nt][2] + b0) * scale;
            float o11 = (acc[mt][nt][3] + b1) * scale;
            if (BF16OUT) {
                __nv_bfloat16* C = (__nv_bfloat16*)Cv;
                *(__nv_bfloat162*)(C + (size_t)r0 * D_ + c)       = __floats2bfloat162_rn(o00, o01);
                *(__nv_bfloat162*)(C + (size_t)(r0 + 8) * D_ + c) = __floats2bfloat162_rn(o10, o11);
            } else {
                float* C = (float*)Cv;
                if (RESID) {
                    float2 r0v = *(const float2*)(resid + (size_t)r0 * D_ + c);
                    float2 r1v = *(const float2*)(resid + (size_t)(r0 + 8) * D_ + c);
                    o00 += r0v.x; o01 += r0v.y;
                    o10 += r1v.x; o11 += r1v.y;
                }
                *(float2*)(C + (size_t)r0 * D_ + c)       = make_float2(o00, o01);
                *(float2*)(C + (size_t)(r0 + 8) * D_ + c) = make_float2(o10, o11);
            }
        }
    }
}

__global__ __launch_bounds__(256) void qkv_kernel(const float* __restrict__ bq,
                                                  const float* __restrict__ bk,
                                                  const float* __restrict__ bv) {
    const float* bi; __nv_bfloat16* C; float scale;
    if (blockIdx.z == 0)      { bi = bq; C = g_qb; scale = 0.125f; }
    else if (blockIdx.z == 1) { bi = bk; C = g_kb; scale = 1.f; }
    else                      { bi = bv; C = g_vb; scale = 1.f; }
    const __nv_bfloat16* W = g_wb + (size_t)blockIdx.z * D_ * D_;
    gemm_bf16<128, false, true>(g_hb, W, bi, nullptr, C, scale, blockIdx.x, blockIdx.y);
}

__global__ __launch_bounds__(256) void out_kernel(const float* __restrict__ bo,
                                                  const float* __restrict__ x,
                                                  float* __restrict__ out) {
    gemm_bf16<64, true, false>(g_ctxb, g_wb + (size_t)3 * D_ * D_, bo, x, out, 1.f,
                               blockIdx.x, blockIdx.y);
}

// ---------------------------------------------------------------------------
// 3) Banded attention (R10 conflict-free config, unchanged)
// ---------------------------------------------------------------------------
#define TQ 32
#define WROWS (TQ + 9)   // 41
#define KVPAD 68

__global__ __launch_bounds__(256) void attn_kernel() {
    __shared__ float Ks[WROWS][KVPAD];
    __shared__ float Vs[WROWS][KVPAD];

    int bh = blockIdx.y;
    int b = bh >> 3, h = bh & 7;
    int t0 = blockIdx.x * TQ;
    int tid = threadIdx.x;

    for (int idx = tid; idx < WROWS * 8; idx += 256) {
        int r = idx >> 3;
        int c = (idx & 7) * 8;
        int jg = t0 - 6 + r;
        if (jg >= 0 && jg < T_) {
            size_t base = ((size_t)(b * T_ + jg)) * D_ + h * DH_ + c;
            uint4 ku = *(const uint4*)(g_kb + base);
            uint4 vu = *(const uint4*)(g_vb + base);
            float2 k01 = __bfloat1622float2(*(__nv_bfloat162*)&ku.x);
            float2 k23 = __bfloat1622float2(*(__nv_bfloat162*)&ku.y);
            float2 k45 = __bfloat1622float2(*(__nv_bfloat162*)&ku.z);
            float2 k67 = __bfloat1622float2(*(__nv_bfloat162*)&ku.w);
            *(float4*)&Ks[r][c]     = make_float4(k01.x, k01.y, k23.x, k23.y);
            *(float4*)&Ks[r][c + 4] = make_float4(k45.x, k45.y, k67.x, k67.y);
            float2 v01 = __bfloat1622float2(*(__nv_bfloat162*)&vu.x);
            float2 v23 = __bfloat1622float2(*(__nv_bfloat162*)&vu.y);
            float2 v45 = __bfloat1622float2(*(__nv_bfloat162*)&vu.z);
            float2 v67 = __bfloat1622float2(*(__nv_bfloat162*)&vu.w);
            *(float4*)&Vs[r][c]     = make_float4(v01.x, v01.y, v23.x, v23.y);
            *(float4*)&Vs[r][c + 4] = make_float4(v45.x, v45.y, v67.x, v67.y);
        } else {
            float4 z = make_float4(0.f, 0.f, 0.f, 0.f);
            *(float4*)&Ks[r][c] = z; *(float4*)&Ks[r][c + 4] = z;
            *(float4*)&Vs[r][c] = z; *(float4*)&Vs[r][c + 4] = z;
        }
    }
    __syncthreads();

    int w = tid >> 5, lane = tid & 31;
    int sub = lane >> 3, di = lane & 7;
    int t = t0 + w * 4 + sub;
    int lo = max(t - 6, 0);
    int hi = min(t + 3, T_ - 1);
    int nw = hi - lo + 1;
    int rbase = lo - (t0 - 6);

    const __nv_bfloat16* qp = g_qb + ((size_t)(b * T_ + t)) * D_ + h * DH_ + di * 4;
    uint2 qa = *(const uint2*)qp;
    uint2 qbv = *(const uint2*)(qp + 32);
    float2 q01 = __bfloat1622float2(*(__nv_bfloat162*)&qa.x);
    float2 q23 = __bfloat1622float2(*(__nv_bfloat162*)&qa.y);
    float2 q45 = __bfloat1622float2(*(__nv_bfloat162*)&qbv.x);
    float2 q67 = __bfloat1622float2(*(__nv_bfloat162*)&qbv.y);

    float sc[10];
    float mx = -1e30f;
    #pragma unroll
    for (int jj = 0; jj < 10; jj++) {
        int r = rbase + jj;
        float4 k0 = *(const float4*)&Ks[r][di * 4];
        float4 k1 = *(const float4*)&Ks[r][32 + di * 4];
        float s = q01.x * k0.x + q01.y * k0.y + q23.x * k0.z + q23.y * k0.w
                + q45.x * k1.x + q45.y * k1.y + q67.x * k1.z + q67.y * k1.w;
        s += __shfl_xor_sync(0xFFFFFFFFu, s, 4);
        s += __shfl_xor_sync(0xFFFFFFFFu, s, 2);
        s += __shfl_xor_sync(0xFFFFFFFFu, s, 1);
        s = (jj < nw) ? s : -1e30f;
        sc[jj] = s;
        mx = fmaxf(mx, s);
    }

    float denom = 0.f;
    float a0 = 0.f, a1 = 0.f, a2 = 0.f, a3 = 0.f;
    float a4 = 0.f, a5 = 0.f, a6 = 0.f, a7 = 0.f;
    #pragma unroll
    for (int jj = 0; jj < 10; jj++) {
        float p = __expf(sc[jj] - mx);
        denom += p;
        int r = rbase + jj;
        float4 v0 = *(const float4*)&Vs[r][di * 4];
        float4 v1 = *(const float4*)&Vs[r][32 + di * 4];
        a0 = fmaf(p, v0.x, a0); a1 = fmaf(p, v0.y, a1);
        a2 = fmaf(p, v0.z, a2); a3 = fmaf(p, v0.w, a3);
        a4 = fmaf(p, v1.x, a4); a5 = fmaf(p, v1.y, a5);
        a6 = fmaf(p, v1.z, a6); a7 = fmaf(p, v1.w, a7);
    }
    float inv = 1.f / denom;

    __nv_bfloat162 o0 = __floats2bfloat162_rn(a0 * inv, a1 * inv);
    __nv_bfloat162 o1 = __floats2bfloat162_rn(a2 * inv, a3 * inv);
    __nv_bfloat162 o2 = __floats2bfloat162_rn(a4 * inv, a5 * inv);
    __nv_bfloat162 o3 = __floats2bfloat162_rn(a6 * inv, a7 * inv);
    __nv_bfloat16* cp = g_ctxb + ((size_t)(b * T_ + t)) * D_ + h * DH_ + di * 4;
    *(uint2*)cp        = make_uint2(*(uint32_t*)&o0, *(uint32_t*)&o1);
    *(uint2*)(cp + 32) = make_uint2(*(uint32_t*)&o2, *(uint32_t*)&o3);
}

// ---------------------------------------------------------------------------
// Launch
// ---------------------------------------------------------------------------
extern "C" void kernel_launch(void* const* d_in, const int* in_sizes, int n_in,
                              void* d_out, int out_size) {
    const float* x     = (const float*)d_in[0];
    const float* gamma = (const float*)d_in[1];
    const float* beta  = (const float*)d_in[2];
    const float* Wq    = (const float*)d_in[3];
    const float* bq    = (const float*)d_in[4];
    const float* Wk    = (const float*)d_in[5];
    const float* bk    = (const float*)d_in[6];
    const float* Wv    = (const float*)d_in[7];
    const float* bv    = (const float*)d_in[8];
    const float* Wo    = (const float*)d_in[9];
    const float* bo    = (const float*)d_in[10];
    float* out = (float*)d_out;

    pre_kernel<<<M_ + 2048, 128>>>(x, gamma, beta, Wq, Wk, Wv, Wo);
    qkv_kernel<<<dim3(D_/128, M_/128, 3), 256>>>(bq, bk, bv);
    attn_kernel<<<dim3(T_/TQ, B_*H_), 256>>>();
    out_kernel<<<dim3(D_/64, M_/128), 256>>>(bo, x, out);
}

// round 12
// speedup vs baseline: 1.5765x; 1.0028x over previous
#include <cuda_runtime.h>
#include <cuda_bf16.h>
#include <math.h>
#include <stdint.h>

#define B_   2
#define T_   2048
#define D_   512
#define H_   8
#define DH_  64
#define M_   (B_*T_)   // 4096 token rows

// Scratch (no cudaMalloc allowed)
__device__ __nv_bfloat16 g_hb[M_*D_];        // LN output, bf16
__device__ __nv_bfloat16 g_wb[4*D_*D_];      // bf16 weights [k][n]: q,k,v,o
__device__ __nv_bfloat16 g_qb[M_*D_];        // q (pre-scaled by 1/8), bf16
__device__ __nv_bfloat16 g_kb[M_*D_];
__device__ __nv_bfloat16 g_vb[M_*D_];
__device__ __nv_bfloat16 g_ctxb[M_*D_];      // attention output, bf16

__device__ __forceinline__ uint32_t smem_u32(const void* p) {
    return (uint32_t)__cvta_generic_to_shared(p);
}

#define CP_ASYNC16(dst, src) \
    asm volatile("cp.async.cg.shared.global [%0], [%1], 16;" :: "r"(dst), "l"(src))
#define CP_COMMIT() asm volatile("cp.async.commit_group;")
#define CP_WAIT(n)  asm volatile("cp.async.wait_group %0;" :: "n"(n))

__device__ __forceinline__ void mma16(float* c, const uint32_t* a, const uint32_t* b) {
    asm volatile(
        "mma.sync.aligned.m16n8k16.row.col.f32.bf16.bf16.f32 "
        "{%0,%1,%2,%3}, {%4,%5,%6,%7}, {%8,%9}, {%0,%1,%2,%3};"
        : "+f"(c[0]), "+f"(c[1]), "+f"(c[2]), "+f"(c[3])
        : "r"(a[0]), "r"(a[1]), "r"(a[2]), "r"(a[3]), "r"(b[0]), "r"(b[1]));
}

// ---------------------------------------------------------------------------
// 1) Fused pre-kernel: LN rows + weight conversion
// ---------------------------------------------------------------------------
__global__ __launch_bounds__(128) void pre_kernel(const float* __restrict__ x,
                                                  const float* __restrict__ gamma,
                                                  const float* __restrict__ beta,
                                                  const float* __restrict__ Wq,
                                                  const float* __restrict__ Wk,
                                                  const float* __restrict__ Wv,
                                                  const float* __restrict__ Wo) {
    int tid = threadIdx.x;
    if (blockIdx.x >= M_) {
        size_t idx = ((size_t)(blockIdx.x - M_) * 128 + tid) * 4;
        int m = (int)(idx >> 18);
        size_t off = idx & ((1u << 18) - 1);
        const float* src;
        if (m == 0) src = Wq; else if (m == 1) src = Wk;
        else if (m == 2) src = Wv; else src = Wo;
        float4 v = *(const float4*)(src + off);
        __nv_bfloat162 lo = __floats2bfloat162_rn(v.x, v.y);
        __nv_bfloat162 hi = __floats2bfloat162_rn(v.z, v.w);
        *(__nv_bfloat162*)(g_wb + idx)     = lo;
        *(__nv_bfloat162*)(g_wb + idx + 2) = hi;
        return;
    }
    int row = blockIdx.x;
    const float4* xr = (const float4*)(x + (size_t)row * D_);
    float4 v = xr[tid];
    float s  = v.x + v.y + v.z + v.w;
    float s2 = v.x * v.x + v.y * v.y + v.z * v.z + v.w * v.w;
    #pragma unroll
    for (int o = 16; o > 0; o >>= 1) {
        s  += __shfl_xor_sync(0xFFFFFFFFu, s,  o);
        s2 += __shfl_xor_sync(0xFFFFFFFFu, s2, o);
    }
    __shared__ float rs[4], rs2[4];
    int wid = tid >> 5, lane = tid & 31;
    if (lane == 0) { rs[wid] = s; rs2[wid] = s2; }
    __syncthreads();
    s  = rs[0]  + rs[1]  + rs[2]  + rs[3];
    s2 = rs2[0] + rs2[1] + rs2[2] + rs2[3];
    float mean = s * (1.0f / D_);
    float var  = s2 * (1.0f / D_) - mean * mean;
    float rstd = rsqrtf(var + 1e-3f);
    float4 g = ((const float4*)gamma)[tid];
    float4 bb = ((const float4*)beta)[tid];
    float o0 = (v.x - mean) * rstd * g.x + bb.x;
    float o1 = (v.y - mean) * rstd * g.y + bb.y;
    float o2 = (v.z - mean) * rstd * g.z + bb.z;
    float o3 = (v.w - mean) * rstd * g.w + bb.w;
    __nv_bfloat162 p0 = __floats2bfloat162_rn(o0, o1);
    __nv_bfloat162 p1 = __floats2bfloat162_rn(o2, o3);
    uint2 pack = make_uint2(*(uint32_t*)&p0, *(uint32_t*)&p1);
    *(uint2*)(g_hb + (size_t)row * D_ + tid * 4) = pack;
}

// ---------------------------------------------------------------------------
// qkv GEMM: BM=128, BN=128, BK=32, 256 threads (measured-good config)
// ---------------------------------------------------------------------------
#define APAD 40    // 32+8 bf16
#define BPAD128 136

__global__ __launch_bounds__(256) void qkv_kernel(const float* __restrict__ bq,
                                                  const float* __restrict__ bk,
                                                  const float* __restrict__ bv) {
    const int K = D_, N = D_;
    const float* bias; __nv_bfloat16* C; float scale;
    if (blockIdx.z == 0)      { bias = bq; C = g_qb; scale = 0.125f; }
    else if (blockIdx.z == 1) { bias = bk; C = g_kb; scale = 1.f; }
    else                      { bias = bv; C = g_vb; scale = 1.f; }
    const __nv_bfloat16* A  = g_hb;
    const __nv_bfloat16* Bm = g_wb + (size_t)blockIdx.z * D_ * D_;

    __shared__ __nv_bfloat16 As[2][128][APAD];
    __shared__ __nv_bfloat16 Bs[2][32][BPAD128];

    int tid = threadIdx.x;
    int lane = tid & 31, wid = tid >> 5;
    int wm = wid & 3, wn = wid >> 2;
    int m0 = blockIdx.y * 128, n0 = blockIdx.x * 128;

    float acc[2][8][4];
    #pragma unroll
    for (int mt = 0; mt < 2; mt++)
        #pragma unroll
        for (int nt = 0; nt < 8; nt++)
            #pragma unroll
            for (int i = 0; i < 4; i++) acc[mt][nt][i] = 0.f;

    int ar = tid >> 2, ac = (tid & 3) * 8;
    int br = tid >> 4, bc = (tid & 15) * 8;

    uint32_t sA = smem_u32(&As[0][0][0]);
    uint32_t sB = smem_u32(&Bs[0][0][0]);
    const uint32_t ABUF = 128 * APAD * 2;
    const uint32_t BBUF = 32 * BPAD128 * 2;

    uint32_t dA0 = sA + (ar * APAD + ac) * 2;
    uint32_t dA1 = sA + ((ar + 64) * APAD + ac) * 2;
    uint32_t dB0 = sB + (br * BPAD128 + bc) * 2;
    uint32_t dB1 = sB + ((br + 16) * BPAD128 + bc) * 2;

    const __nv_bfloat16* gA0 = A + (size_t)(m0 + ar) * K + ac;
    const __nv_bfloat16* gA1 = A + (size_t)(m0 + ar + 64) * K + ac;
    const __nv_bfloat16* gB0 = Bm + (size_t)br * N + n0 + bc;
    const __nv_bfloat16* gB1 = Bm + (size_t)(br + 16) * N + n0 + bc;

    CP_ASYNC16(dA0, gA0);
    CP_ASYNC16(dA1, gA1);
    CP_ASYNC16(dB0, gB0);
    CP_ASYNC16(dB1, gB1);
    CP_COMMIT();

    const int NIT = K / 32;
    for (int it = 0; it < NIT; it++) {
        int buf = it & 1;
        CP_WAIT(0);
        __syncthreads();
        if (it + 1 < NIT) {
            int nb = (it + 1) & 1;
            int k0 = (it + 1) * 32;
            CP_ASYNC16(dA0 + nb * ABUF, gA0 + k0);
            CP_ASYNC16(dA1 + nb * ABUF, gA1 + k0);
            CP_ASYNC16(dB0 + nb * BBUF, gB0 + (size_t)k0 * N);
            CP_ASYNC16(dB1 + nb * BBUF, gB1 + (size_t)k0 * N);
            CP_COMMIT();
        }
        uint32_t aBase = sA + buf * ABUF;
        uint32_t bBase = sB + buf * BBUF;
        #pragma unroll
        for (int ks = 0; ks < 2; ks++) {
            int kq = ks * 16;
            uint32_t a[2][4], bf[4][4];
            #pragma unroll
            for (int mt = 0; mt < 2; mt++) {
                int row = wm * 32 + mt * 16 + (lane & 15);
                int col = kq + ((lane >> 4) * 8);
                uint32_t addr = aBase + (row * APAD + col) * 2;
                asm volatile("ldmatrix.sync.aligned.m8n8.x4.shared.b16 {%0,%1,%2,%3}, [%4];"
                             : "=r"(a[mt][0]), "=r"(a[mt][1]), "=r"(a[mt][2]), "=r"(a[mt][3])
                             : "r"(addr));
            }
            #pragma unroll
            for (int np = 0; np < 4; np++) {
                int row = kq + (lane & 15);
                int col = wn * 64 + np * 16 + ((lane >> 4) * 8);
                uint32_t addr = bBase + (row * BPAD128 + col) * 2;
                asm volatile("ldmatrix.sync.aligned.m8n8.x4.trans.shared.b16 {%0,%1,%2,%3}, [%4];"
                             : "=r"(bf[np][0]), "=r"(bf[np][1]), "=r"(bf[np][2]), "=r"(bf[np][3])
                             : "r"(addr));
            }
            #pragma unroll
            for (int mt = 0; mt < 2; mt++)
                #pragma unroll
                for (int nt = 0; nt < 8; nt++)
                    mma16(acc[mt][nt], a[mt], &bf[nt >> 1][(nt & 1) * 2]);
        }
    }

    #pragma unroll
    for (int mt = 0; mt < 2; mt++) {
        #pragma unroll
        for (int nt = 0; nt < 8; nt++) {
            int r0 = m0 + wm * 32 + mt * 16 + (lane >> 2);
            int c  = n0 + wn * 64 + nt * 8 + (lane & 3) * 2;
            float b0 = bias[c], b1 = bias[c + 1];
            float o00 = (acc[mt][nt][0] + b0) * scale;
            float o01 = (acc[mt][nt][1] + b1) * scale;
            float o10 = (acc[mt][nt][2] + b0) * scale;
            float o11 = (acc[mt][nt][3] + b1) * scale;
            *(__nv_bfloat162*)(C + (size_t)r0 * D_ + c)       = __floats2bfloat162_rn(o00, o01);
            *(__nv_bfloat162*)(C + (size_t)(r0 + 8) * D_ + c) = __floats2bfloat162_rn(o10, o11);
        }
    }
}

// ---------------------------------------------------------------------------
// out GEMM: BM=64, BN=64, BK=32, 128 threads (2x2 warps, warp tile 32x32)
// grid 512 CTAs for latency hiding; +bias +resid, fp32 out
// ---------------------------------------------------------------------------
#define BPAD64 72

__global__ __launch_bounds__(128) void out_kernel(const float* __restrict__ bo,
                                                  const float* __restrict__ x,
                                                  float* __restrict__ out) {
    const int K = D_, N = D_;
    const __nv_bfloat16* A  = g_ctxb;
    const __nv_bfloat16* Bm = g_wb + (size_t)3 * D_ * D_;

    __shared__ __nv_bfloat16 As[2][64][APAD];
    __shared__ __nv_bfloat16 Bs[2][32][BPAD64];

    int tid = threadIdx.x;
    int lane = tid & 31, wid = tid >> 5;
    int wm = wid & 1, wn = wid >> 1;          // 2x2 warp grid
    int m0 = blockIdx.y * 64, n0 = blockIdx.x * 64;

    float acc[2][4][4];
    #pragma unroll
    for (int mt = 0; mt < 2; mt++)
        #pragma unroll
        for (int nt = 0; nt < 4; nt++)
            #pragma unroll
            for (int i = 0; i < 4; i++) acc[mt][nt][i] = 0.f;

    // A: 64x32 = 256 chunks of 16B -> 2/thread; B: 32x64 = 256 -> 2/thread
    int ar = tid >> 2, ac = (tid & 3) * 8;    // rows ar, ar+32
    int br = tid >> 3, bc = (tid & 7) * 8;    // rows br, br+16

    uint32_t sA = smem_u32(&As[0][0][0]);
    uint32_t sB = smem_u32(&Bs[0][0][0]);
    const uint32_t ABUF = 64 * APAD * 2;
    const uint32_t BBUF = 32 * BPAD64 * 2;

    uint32_t dA0 = sA + (ar * APAD + ac) * 2;
    uint32_t dA1 = sA + ((ar + 32) * APAD + ac) * 2;
    uint32_t dB0 = sB + (br * BPAD64 + bc) * 2;
    uint32_t dB1 = sB + ((br + 16) * BPAD64 + bc) * 2;

    const __nv_bfloat16* gA0 = A + (size_t)(m0 + ar) * K + ac;
    const __nv_bfloat16* gA1 = A + (size_t)(m0 + ar + 32) * K + ac;
    const __nv_bfloat16* gB0 = Bm + (size_t)br * N + n0 + bc;
    const __nv_bfloat16* gB1 = Bm + (size_t)(br + 16) * N + n0 + bc;

    CP_ASYNC16(dA0, gA0);
    CP_ASYNC16(dA1, gA1);
    CP_ASYNC16(dB0, gB0);
    CP_ASYNC16(dB1, gB1);
    CP_COMMIT();

    const int NIT = K / 32;
    for (int it = 0; it < NIT; it++) {
        int buf = it & 1;
        CP_WAIT(0);
        __syncthreads();
        if (it + 1 < NIT) {
            int nb = (it + 1) & 1;
            int k0 = (it + 1) * 32;
            CP_ASYNC16(dA0 + nb * ABUF, gA0 + k0);
            CP_ASYNC16(dA1 + nb * ABUF, gA1 + k0);
            CP_ASYNC16(dB0 + nb * BBUF, gB0 + (size_t)k0 * N);
            CP_ASYNC16(dB1 + nb * BBUF, gB1 + (size_t)k0 * N);
            CP_COMMIT();
        }
        uint32_t aBase = sA + buf * ABUF;
        uint32_t bBase = sB + buf * BBUF;
        #pragma unroll
        for (int ks = 0; ks < 2; ks++) {
            int kq = ks * 16;
            uint32_t a[2][4], bf[2][4];
            #pragma unroll
            for (int mt = 0; mt < 2; mt++) {
                int row = wm * 32 + mt * 16 + (lane & 15);
                int col = kq + ((lane >> 4) * 8);
                uint32_t addr = aBase + (row * APAD + col) * 2;
                asm volatile("ldmatrix.sync.aligned.m8n8.x4.shared.b16 {%0,%1,%2,%3}, [%4];"
                             : "=r"(a[mt][0]), "=r"(a[mt][1]), "=r"(a[mt][2]), "=r"(a[mt][3])
                             : "r"(addr));
            }
            #pragma unroll
            for (int np = 0; np < 2; np++) {
                int row = kq + (lane & 15);
                int col = wn * 32 + np * 16 + ((lane >> 4) * 8);
                uint32_t addr = bBase + (row * BPAD64 + col) * 2;
                asm volatile("ldmatrix.sync.aligned.m8n8.x4.trans.shared.b16 {%0,%1,%2,%3}, [%4];"
                             : "=r"(bf[np][0]), "=r"(bf[np][1]), "=r"(bf[np][2]), "=r"(bf[np][3])
                             : "r"(addr));
            }
            #pragma unroll
            for (int mt = 0; mt < 2; mt++)
                #pragma unroll
                for (int nt = 0; nt < 4; nt++)
                    mma16(acc[mt][nt], a[mt], &bf[nt >> 1][(nt & 1) * 2]);
        }
    }

    #pragma unroll
    for (int mt = 0; mt < 2; mt++) {
        #pragma unroll
        for (int nt = 0; nt < 4; nt++) {
            int r0 = m0 + wm * 32 + mt * 16 + (lane >> 2);
            int c  = n0 + wn * 32 + nt * 8 + (lane & 3) * 2;
            float b0 = bo[c], b1 = bo[c + 1];
            float o00 = acc[mt][nt][0] + b0;
            float o01 = acc[mt][nt][1] + b1;
            float o10 = acc[mt][nt][2] + b0;
            float o11 = acc[mt][nt][3] + b1;
            float2 r0v = *(const float2*)(x + (size_t)r0 * D_ + c);
            float2 r1v = *(const float2*)(x + (size_t)(r0 + 8) * D_ + c);
            o00 += r0v.x; o01 += r0v.y;
            o10 += r1v.x; o11 += r1v.y;
            *(float2*)(out + (size_t)r0 * D_ + c)       = make_float2(o00, o01);
            *(float2*)(out + (size_t)(r0 + 8) * D_ + c) = make_float2(o10, o11);
        }
    }
}

// ---------------------------------------------------------------------------
// 3) Banded attention (R10 conflict-free config, unchanged)
// ---------------------------------------------------------------------------
#define TQ 32
#define WROWS (TQ + 9)   // 41
#define KVPAD 68

__global__ __launch_bounds__(256) void attn_kernel() {
    __shared__ float Ks[WROWS][KVPAD];
    __shared__ float Vs[WROWS][KVPAD];

    int bh = blockIdx.y;
    int b = bh >> 3, h = bh & 7;
    int t0 = blockIdx.x * TQ;
    int tid = threadIdx.x;

    for (int idx = tid; idx < WROWS * 8; idx += 256) {
        int r = idx >> 3;
        int c = (idx & 7) * 8;
        int jg = t0 - 6 + r;
        if (jg >= 0 && jg < T_) {
            size_t base = ((size_t)(b * T_ + jg)) * D_ + h * DH_ + c;
            uint4 ku = *(const uint4*)(g_kb + base);
            uint4 vu = *(const uint4*)(g_vb + base);
            float2 k01 = __bfloat1622float2(*(__nv_bfloat162*)&ku.x);
            float2 k23 = __bfloat1622float2(*(__nv_bfloat162*)&ku.y);
            float2 k45 = __bfloat1622float2(*(__nv_bfloat162*)&ku.z);
            float2 k67 = __bfloat1622float2(*(__nv_bfloat162*)&ku.w);
            *(float4*)&Ks[r][c]     = make_float4(k01.x, k01.y, k23.x, k23.y);
            *(float4*)&Ks[r][c + 4] = make_float4(k45.x, k45.y, k67.x, k67.y);
            float2 v01 = __bfloat1622float2(*(__nv_bfloat162*)&vu.x);
            float2 v23 = __bfloat1622float2(*(__nv_bfloat162*)&vu.y);
            float2 v45 = __bfloat1622float2(*(__nv_bfloat162*)&vu.z);
            float2 v67 = __bfloat1622float2(*(__nv_bfloat162*)&vu.w);
            *(float4*)&Vs[r][c]     = make_float4(v01.x, v01.y, v23.x, v23.y);
            *(float4*)&Vs[r][c + 4] = make_float4(v45.x, v45.y, v67.x, v67.y);
        } else {
            float4 z = make_float4(0.f, 0.f, 0.f, 0.f);
            *(float4*)&Ks[r][c] = z; *(float4*)&Ks[r][c + 4] = z;
            *(float4*)&Vs[r][c] = z; *(float4*)&Vs[r][c + 4] = z;
        }
    }
    __syncthreads();

    int w = tid >> 5, lane = tid & 31;
    int sub = lane >> 3, di = lane & 7;
    int t = t0 + w * 4 + sub;
    int lo = max(t - 6, 0);
    int hi = min(t + 3, T_ - 1);
    int nw = hi - lo + 1;
    int rbase = lo - (t0 - 6);

    const __nv_bfloat16* qp = g_qb + ((size_t)(b * T_ + t)) * D_ + h * DH_ + di * 4;
    uint2 qa = *(const uint2*)qp;
    uint2 qbv = *(const uint2*)(qp + 32);
    float2 q01 = __bfloat1622float2(*(__nv_bfloat162*)&qa.x);
    float2 q23 = __bfloat1622float2(*(__nv_bfloat162*)&qa.y);
    float2 q45 = __bfloat1622float2(*(__nv_bfloat162*)&qbv.x);
    float2 q67 = __bfloat1622float2(*(__nv_bfloat162*)&qbv.y);

    float sc[10];
    float mx = -1e30f;
    #pragma unroll
    for (int jj = 0; jj < 10; jj++) {
        int r = rbase + jj;
        float4 k0 = *(const float4*)&Ks[r][di * 4];
        float4 k1 = *(const float4*)&Ks[r][32 + di * 4];
        float s = q01.x * k0.x + q01.y * k0.y + q23.x * k0.z + q23.y * k0.w
                + q45.x * k1.x + q45.y * k1.y + q67.x * k1.z + q67.y * k1.w;
        s += __shfl_xor_sync(0xFFFFFFFFu, s, 4);
        s += __shfl_xor_sync(0xFFFFFFFFu, s, 2);
        s += __shfl_xor_sync(0xFFFFFFFFu, s, 1);
        s = (jj < nw) ? s : -1e30f;
        sc[jj] = s;
        mx = fmaxf(mx, s);
    }

    float denom = 0.f;
    float a0 = 0.f, a1 = 0.f, a2 = 0.f, a3 = 0.f;
    float a4 = 0.f, a5 = 0.f, a6 = 0.f, a7 = 0.f;
    #pragma unroll
    for (int jj = 0; jj < 10; jj++) {
        float p = __expf(sc[jj] - mx);
        denom += p;
        int r = rbase + jj;
        float4 v0 = *(const float4*)&Vs[r][di * 4];
        float4 v1 = *(const float4*)&Vs[r][32 + di * 4];
        a0 = fmaf(p, v0.x, a0); a1 = fmaf(p, v0.y, a1);
        a2 = fmaf(p, v0.z, a2); a3 = fmaf(p, v0.w, a3);
        a4 = fmaf(p, v1.x, a4); a5 = fmaf(p, v1.y, a5);
        a6 = fmaf(p, v1.z, a6); a7 = fmaf(p, v1.w, a7);
    }
    float inv = 1.f / denom;

    __nv_bfloat162 o0 = __floats2bfloat162_rn(a0 * inv, a1 * inv);
    __nv_bfloat162 o1 = __floats2bfloat162_rn(a2 * inv, a3 * inv);
    __nv_bfloat162 o2 = __floats2bfloat162_rn(a4 * inv, a5 * inv);
    __nv_bfloat162 o3 = __floats2bfloat162_rn(a6 * inv, a7 * inv);
    __nv_bfloat16* cp = g_ctxb + ((size_t)(b * T_ + t)) * D_ + h * DH_ + di * 4;
    *(uint2*)cp        = make_uint2(*(uint32_t*)&o0, *(uint32_t*)&o1);
    *(uint2*)(cp + 32) = make_uint2(*(uint32_t*)&o2, *(uint32_t*)&o3);
}

// ---------------------------------------------------------------------------
// Launch
// ---------------------------------------------------------------------------
extern "C" void kernel_launch(void* const* d_in, const int* in_sizes, int n_in,
                              void* d_out, int out_size) {
    const float* x     = (const float*)d_in[0];
    const float* gamma = (const float*)d_in[1];
    const float* beta  = (const float*)d_in[2];
    const float* Wq    = (const float*)d_in[3];
    const float* bq    = (const float*)d_in[4];
    const float* Wk    = (const float*)d_in[5];
    const float* bk    = (const float*)d_in[6];
    const float* Wv    = (const float*)d_in[7];
    const float* bv    = (const float*)d_in[8];
    const float* Wo    = (const float*)d_in[9];
    const float* bo    = (const float*)d_in[10];
    float* out = (float*)d_out;

    pre_kernel<<<M_ + 2048, 128>>>(x, gamma, beta, Wq, Wk, Wv, Wo);
    qkv_kernel<<<dim3(D_/128, M_/128, 3), 256>>>(bq, bk, bv);
    attn_kernel<<<dim3(T_/TQ, B_*H_), 256>>>();
    out_kernel<<<dim3(D_/64, M_/64), 128>>>(bo, x, out);
}

// round 13
// speedup vs baseline: 1.5818x; 1.0034x over previous
#include <cuda_runtime.h>
#include <cuda_bf16.h>
#include <math.h>
#include <stdint.h>

#define B_   2
#define T_   2048
#define D_   512
#define H_   8
#define DH_  64
#define M_   (B_*T_)   // 4096 token rows

// Scratch (no cudaMalloc allowed)
__device__ __nv_bfloat16 g_hb[M_*D_];        // LN output, bf16
__device__ __nv_bfloat16 g_wb[4*D_*D_];      // bf16 weights [k][n]: q,k,v,o
__device__ __nv_bfloat16 g_qb[M_*D_];        // q (pre-scaled by 1/8), bf16
__device__ __nv_bfloat16 g_kb[M_*D_];
__device__ __nv_bfloat16 g_vb[M_*D_];
__device__ __nv_bfloat16 g_ctxb[M_*D_];      // attention output, bf16

__device__ __forceinline__ uint32_t smem_u32(const void* p) {
    return (uint32_t)__cvta_generic_to_shared(p);
}

#define CP_ASYNC16(dst, src) \
    asm volatile("cp.async.cg.shared.global [%0], [%1], 16;" :: "r"(dst), "l"(src))
#define CP_COMMIT() asm volatile("cp.async.commit_group;")
#define CP_WAIT(n)  asm volatile("cp.async.wait_group %0;" :: "n"(n))

__device__ __forceinline__ void mma16(float* c, const uint32_t* a, const uint32_t* b) {
    asm volatile(
        "mma.sync.aligned.m16n8k16.row.col.f32.bf16.bf16.f32 "
        "{%0,%1,%2,%3}, {%4,%5,%6,%7}, {%8,%9}, {%0,%1,%2,%3};"
        : "+f"(c[0]), "+f"(c[1]), "+f"(c[2]), "+f"(c[3])
        : "r"(a[0]), "r"(a[1]), "r"(a[2]), "r"(a[3]), "r"(b[0]), "r"(b[1]));
}

// ---------------------------------------------------------------------------
// 1) Fused pre-kernel: LN rows + weight conversion
// ---------------------------------------------------------------------------
__global__ __launch_bounds__(128) void pre_kernel(const float* __restrict__ x,
                                                  const float* __restrict__ gamma,
                                                  const float* __restrict__ beta,
                                                  const float* __restrict__ Wq,
                                                  const float* __restrict__ Wk,
                                                  const float* __restrict__ Wv,
                                                  const float* __restrict__ Wo) {
    int tid = threadIdx.x;
    if (blockIdx.x >= M_) {
        size_t idx = ((size_t)(blockIdx.x - M_) * 128 + tid) * 4;
        int m = (int)(idx >> 18);
        size_t off = idx & ((1u << 18) - 1);
        const float* src;
        if (m == 0) src = Wq; else if (m == 1) src = Wk;
        else if (m == 2) src = Wv; else src = Wo;
        float4 v = *(const float4*)(src + off);
        __nv_bfloat162 lo = __floats2bfloat162_rn(v.x, v.y);
        __nv_bfloat162 hi = __floats2bfloat162_rn(v.z, v.w);
        *(__nv_bfloat162*)(g_wb + idx)     = lo;
        *(__nv_bfloat162*)(g_wb + idx + 2) = hi;
        return;
    }
    int row = blockIdx.x;
    const float4* xr = (const float4*)(x + (size_t)row * D_);
    float4 v = xr[tid];
    float s  = v.x + v.y + v.z + v.w;
    float s2 = v.x * v.x + v.y * v.y + v.z * v.z + v.w * v.w;
    #pragma unroll
    for (int o = 16; o > 0; o >>= 1) {
        s  += __shfl_xor_sync(0xFFFFFFFFu, s,  o);
        s2 += __shfl_xor_sync(0xFFFFFFFFu, s2, o);
    }
    __shared__ float rs[4], rs2[4];
    int wid = tid >> 5, lane = tid & 31;
    if (lane == 0) { rs[wid] = s; rs2[wid] = s2; }
    __syncthreads();
    s  = rs[0]  + rs[1]  + rs[2]  + rs[3];
    s2 = rs2[0] + rs2[1] + rs2[2] + rs2[3];
    float mean = s * (1.0f / D_);
    float var  = s2 * (1.0f / D_) - mean * mean;
    float rstd = rsqrtf(var + 1e-3f);
    float4 g = ((const float4*)gamma)[tid];
    float4 bb = ((const float4*)beta)[tid];
    float o0 = (v.x - mean) * rstd * g.x + bb.x;
    float o1 = (v.y - mean) * rstd * g.y + bb.y;
    float o2 = (v.z - mean) * rstd * g.z + bb.z;
    float o3 = (v.w - mean) * rstd * g.w + bb.w;
    __nv_bfloat162 p0 = __floats2bfloat162_rn(o0, o1);
    __nv_bfloat162 p1 = __floats2bfloat162_rn(o2, o3);
    uint2 pack = make_uint2(*(uint32_t*)&p0, *(uint32_t*)&p1);
    *(uint2*)(g_hb + (size_t)row * D_ + tid * 4) = pack;
}

// ---------------------------------------------------------------------------
// qkv GEMM: BM=128, BN=128, BK=32, 256 threads, 2-stage (measured-good)
// ---------------------------------------------------------------------------
#define APAD 40    // 32+8 bf16
#define BPAD128 136

__global__ __launch_bounds__(256) void qkv_kernel(const float* __restrict__ bq,
                                                  const float* __restrict__ bk,
                                                  const float* __restrict__ bv) {
    const int K = D_, N = D_;
    const float* bias; __nv_bfloat16* C; float scale;
    if (blockIdx.z == 0)      { bias = bq; C = g_qb; scale = 0.125f; }
    else if (blockIdx.z == 1) { bias = bk; C = g_kb; scale = 1.f; }
    else                      { bias = bv; C = g_vb; scale = 1.f; }
    const __nv_bfloat16* A  = g_hb;
    const __nv_bfloat16* Bm = g_wb + (size_t)blockIdx.z * D_ * D_;

    __shared__ __nv_bfloat16 As[2][128][APAD];
    __shared__ __nv_bfloat16 Bs[2][32][BPAD128];

    int tid = threadIdx.x;
    int lane = tid & 31, wid = tid >> 5;
    int wm = wid & 3, wn = wid >> 2;
    int m0 = blockIdx.y * 128, n0 = blockIdx.x * 128;

    float acc[2][8][4];
    #pragma unroll
    for (int mt = 0; mt < 2; mt++)
        #pragma unroll
        for (int nt = 0; nt < 8; nt++)
            #pragma unroll
            for (int i = 0; i < 4; i++) acc[mt][nt][i] = 0.f;

    int ar = tid >> 2, ac = (tid & 3) * 8;
    int br = tid >> 4, bc = (tid & 15) * 8;

    uint32_t sA = smem_u32(&As[0][0][0]);
    uint32_t sB = smem_u32(&Bs[0][0][0]);
    const uint32_t ABUF = 128 * APAD * 2;
    const uint32_t BBUF = 32 * BPAD128 * 2;

    uint32_t dA0 = sA + (ar * APAD + ac) * 2;
    uint32_t dA1 = sA + ((ar + 64) * APAD + ac) * 2;
    uint32_t dB0 = sB + (br * BPAD128 + bc) * 2;
    uint32_t dB1 = sB + ((br + 16) * BPAD128 + bc) * 2;

    const __nv_bfloat16* gA0 = A + (size_t)(m0 + ar) * K + ac;
    const __nv_bfloat16* gA1 = A + (size_t)(m0 + ar + 64) * K + ac;
    const __nv_bfloat16* gB0 = Bm + (size_t)br * N + n0 + bc;
    const __nv_bfloat16* gB1 = Bm + (size_t)(br + 16) * N + n0 + bc;

    CP_ASYNC16(dA0, gA0);
    CP_ASYNC16(dA1, gA1);
    CP_ASYNC16(dB0, gB0);
    CP_ASYNC16(dB1, gB1);
    CP_COMMIT();

    const int NIT = K / 32;
    for (int it = 0; it < NIT; it++) {
        int buf = it & 1;
        CP_WAIT(0);
        __syncthreads();
        if (it + 1 < NIT) {
            int nb = (it + 1) & 1;
            int k0 = (it + 1) * 32;
            CP_ASYNC16(dA0 + nb * ABUF, gA0 + k0);
            CP_ASYNC16(dA1 + nb * ABUF, gA1 + k0);
            CP_ASYNC16(dB0 + nb * BBUF, gB0 + (size_t)k0 * N);
            CP_ASYNC16(dB1 + nb * BBUF, gB1 + (size_t)k0 * N);
            CP_COMMIT();
        }
        uint32_t aBase = sA + buf * ABUF;
        uint32_t bBase = sB + buf * BBUF;
        #pragma unroll
        for (int ks = 0; ks < 2; ks++) {
            int kq = ks * 16;
            uint32_t a[2][4], bf[4][4];
            #pragma unroll
            for (int mt = 0; mt < 2; mt++) {
                int row = wm * 32 + mt * 16 + (lane & 15);
                int col = kq + ((lane >> 4) * 8);
                uint32_t addr = aBase + (row * APAD + col) * 2;
                asm volatile("ldmatrix.sync.aligned.m8n8.x4.shared.b16 {%0,%1,%2,%3}, [%4];"
                             : "=r"(a[mt][0]), "=r"(a[mt][1]), "=r"(a[mt][2]), "=r"(a[mt][3])
                             : "r"(addr));
            }
            #pragma unroll
            for (int np = 0; np < 4; np++) {
                int row = kq + (lane & 15);
                int col = wn * 64 + np * 16 + ((lane >> 4) * 8);
                uint32_t addr = bBase + (row * BPAD128 + col) * 2;
                asm volatile("ldmatrix.sync.aligned.m8n8.x4.trans.shared.b16 {%0,%1,%2,%3}, [%4];"
                             : "=r"(bf[np][0]), "=r"(bf[np][1]), "=r"(bf[np][2]), "=r"(bf[np][3])
                             : "r"(addr));
            }
            #pragma unroll
            for (int mt = 0; mt < 2; mt++)
                #pragma unroll
                for (int nt = 0; nt < 8; nt++)
                    mma16(acc[mt][nt], a[mt], &bf[nt >> 1][(nt & 1) * 2]);
        }
    }

    #pragma unroll
    for (int mt = 0; mt < 2; mt++) {
        #pragma unroll
        for (int nt = 0; nt < 8; nt++) {
            int r0 = m0 + wm * 32 + mt * 16 + (lane >> 2);
            int c  = n0 + wn * 64 + nt * 8 + (lane & 3) * 2;
            float b0 = bias[c], b1 = bias[c + 1];
            float o00 = (acc[mt][nt][0] + b0) * scale;
            float o01 = (acc[mt][nt][1] + b1) * scale;
            float o10 = (acc[mt][nt][2] + b0) * scale;
            float o11 = (acc[mt][nt][3] + b1) * scale;
            *(__nv_bfloat162*)(C + (size_t)r0 * D_ + c)       = __floats2bfloat162_rn(o00, o01);
            *(__nv_bfloat162*)(C + (size_t)(r0 + 8) * D_ + c) = __floats2bfloat162_rn(o10, o11);
        }
    }
}

// ---------------------------------------------------------------------------
// out GEMM: BM=64, BN=64, BK=32, 128 threads, 3-STAGE cp.async pipeline
// (prefetch distance 2, CP_WAIT(1), one sync/iter)
// ---------------------------------------------------------------------------
#define BPAD64 72
#define ONSTG 3

__global__ __launch_bounds__(128) void out_kernel(const float* __restrict__ bo,
                                                  const float* __restrict__ x,
                                                  float* __restrict__ out) {
    const int K = D_, N = D_;
    const __nv_bfloat16* A  = g_ctxb;
    const __nv_bfloat16* Bm = g_wb + (size_t)3 * D_ * D_;

    __shared__ __nv_bfloat16 As[ONSTG][64][APAD];
    __shared__ __nv_bfloat16 Bs[ONSTG][32][BPAD64];

    int tid = threadIdx.x;
    int lane = tid & 31, wid = tid >> 5;
    int wm = wid & 1, wn = wid >> 1;          // 2x2 warp grid
    int m0 = blockIdx.y * 64, n0 = blockIdx.x * 64;

    float acc[2][4][4];
    #pragma unroll
    for (int mt = 0; mt < 2; mt++)
        #pragma unroll
        for (int nt = 0; nt < 4; nt++)
            #pragma unroll
            for (int i = 0; i < 4; i++) acc[mt][nt][i] = 0.f;

    int ar = tid >> 2, ac = (tid & 3) * 8;    // rows ar, ar+32
    int br = tid >> 3, bc = (tid & 7) * 8;    // rows br, br+16

    uint32_t sA = smem_u32(&As[0][0][0]);
    uint32_t sB = smem_u32(&Bs[0][0][0]);
    const uint32_t ABUF = 64 * APAD * 2;
    const uint32_t BBUF = 32 * BPAD64 * 2;

    uint32_t dA0 = sA + (ar * APAD + ac) * 2;
    uint32_t dA1 = sA + ((ar + 32) * APAD + ac) * 2;
    uint32_t dB0 = sB + (br * BPAD64 + bc) * 2;
    uint32_t dB1 = sB + ((br + 16) * BPAD64 + bc) * 2;

    const __nv_bfloat16* gA0 = A + (size_t)(m0 + ar) * K + ac;
    const __nv_bfloat16* gA1 = A + (size_t)(m0 + ar + 32) * K + ac;
    const __nv_bfloat16* gB0 = Bm + (size_t)br * N + n0 + bc;
    const __nv_bfloat16* gB1 = Bm + (size_t)(br + 16) * N + n0 + bc;

    const int NIT = K / 32;   // 16
    // prologue: stages 0,1 (two commit groups)
    #pragma unroll
    for (int s = 0; s < 2; s++) {
        int k0 = s * 32;
        CP_ASYNC16(dA0 + s * ABUF, gA0 + k0);
        CP_ASYNC16(dA1 + s * ABUF, gA1 + k0);
        CP_ASYNC16(dB0 + s * BBUF, gB0 + (size_t)k0 * N);
        CP_ASYNC16(dB1 + s * BBUF, gB1 + (size_t)k0 * N);
        CP_COMMIT();
    }

    for (int it = 0; it < NIT; it++) {
        CP_WAIT(1);              // stage `it` landed; one group may remain in flight
        __syncthreads();         // also: everyone done reading stage (it+2)%3 (read at it-1)
        if (it + 2 < NIT) {
            int sb = (it + 2) % ONSTG;
            int k0 = (it + 2) * 32;
            CP_ASYNC16(dA0 + sb * ABUF, gA0 + k0);
            CP_ASYNC16(dA1 + sb * ABUF, gA1 + k0);
            CP_ASYNC16(dB0 + sb * BBUF, gB0 + (size_t)k0 * N);
            CP_ASYNC16(dB1 + sb * BBUF, gB1 + (size_t)k0 * N);
            CP_COMMIT();
        }
        int buf = it % ONSTG;
        uint32_t aBase = sA + buf * ABUF;
        uint32_t bBase = sB + buf * BBUF;
        #pragma unroll
        for (int ks = 0; ks < 2; ks++) {
            int kq = ks * 16;
            uint32_t a[2][4], bf[2][4];
            #pragma unroll
            for (int mt = 0; mt < 2; mt++) {
                int row = wm * 32 + mt * 16 + (lane & 15);
                int col = kq + ((lane >> 4) * 8);
                uint32_t addr = aBase + (row * APAD + col) * 2;
                asm volatile("ldmatrix.sync.aligned.m8n8.x4.shared.b16 {%0,%1,%2,%3}, [%4];"
                             : "=r"(a[mt][0]), "=r"(a[mt][1]), "=r"(a[mt][2]), "=r"(a[mt][3])
                             : "r"(addr));
            }
            #pragma unroll
            for (int np = 0; np < 2; np++) {
                int row = kq + (lane & 15);
                int col = wn * 32 + np * 16 + ((lane >> 4) * 8);
                uint32_t addr = bBase + (row * BPAD64 + col) * 2;
                asm volatile("ldmatrix.sync.aligned.m8n8.x4.trans.shared.b16 {%0,%1,%2,%3}, [%4];"
                             : "=r"(bf[np][0]), "=r"(bf[np][1]), "=r"(bf[np][2]), "=r"(bf[np][3])
                             : "r"(addr));
            }
            #pragma unroll
            for (int mt = 0; mt < 2; mt++)
                #pragma unroll
                for (int nt = 0; nt < 4; nt++)
                    mma16(acc[mt][nt], a[mt], &bf[nt >> 1][(nt & 1) * 2]);
        }
    }

    #pragma unroll
    for (int mt = 0; mt < 2; mt++) {
        #pragma unroll
        for (int nt = 0; nt < 4; nt++) {
            int r0 = m0 + wm * 32 + mt * 16 + (lane >> 2);
            int c  = n0 + wn * 32 + nt * 8 + (lane & 3) * 2;
            float b0 = bo[c], b1 = bo[c + 1];
            float o00 = acc[mt][nt][0] + b0;
            float o01 = acc[mt][nt][1] + b1;
            float o10 = acc[mt][nt][2] + b0;
            float o11 = acc[mt][nt][3] + b1;
            float2 r0v = *(const float2*)(x + (size_t)r0 * D_ + c);
            float2 r1v = *(const float2*)(x + (size_t)(r0 + 8) * D_ + c);
            o00 += r0v.x; o01 += r0v.y;
            o10 += r1v.x; o11 += r1v.y;
            *(float2*)(out + (size_t)r0 * D_ + c)       = make_float2(o00, o01);
            *(float2*)(out + (size_t)(r0 + 8) * D_ + c) = make_float2(o10, o11);
        }
    }
}

// ---------------------------------------------------------------------------
// 3) Banded attention (R10 conflict-free config, unchanged)
// ---------------------------------------------------------------------------
#define TQ 32
#define WROWS (TQ + 9)   // 41
#define KVPAD 68

__global__ __launch_bounds__(256) void attn_kernel() {
    __shared__ float Ks[WROWS][KVPAD];
    __shared__ float Vs[WROWS][KVPAD];

    int bh = blockIdx.y;
    int b = bh >> 3, h = bh & 7;
    int t0 = blockIdx.x * TQ;
    int tid = threadIdx.x;

    for (int idx = tid; idx < WROWS * 8; idx += 256) {
        int r = idx >> 3;
        int c = (idx & 7) * 8;
        int jg = t0 - 6 + r;
        if (jg >= 0 && jg < T_) {
            size_t base = ((size_t)(b * T_ + jg)) * D_ + h * DH_ + c;
            uint4 ku = *(const uint4*)(g_kb + base);
            uint4 vu = *(const uint4*)(g_vb + base);
            float2 k01 = __bfloat1622float2(*(__nv_bfloat162*)&ku.x);
            float2 k23 = __bfloat1622float2(*(__nv_bfloat162*)&ku.y);
            float2 k45 = __bfloat1622float2(*(__nv_bfloat162*)&ku.z);
            float2 k67 = __bfloat1622float2(*(__nv_bfloat162*)&ku.w);
            *(float4*)&Ks[r][c]     = make_float4(k01.x, k01.y, k23.x, k23.y);
            *(float4*)&Ks[r][c + 4] = make_float4(k45.x, k45.y, k67.x, k67.y);
            float2 v01 = __bfloat1622float2(*(__nv_bfloat162*)&vu.x);
            float2 v23 = __bfloat1622float2(*(__nv_bfloat162*)&vu.y);
            float2 v45 = __bfloat1622float2(*(__nv_bfloat162*)&vu.z);
            float2 v67 = __bfloat1622float2(*(__nv_bfloat162*)&vu.w);
            *(float4*)&Vs[r][c]     = make_float4(v01.x, v01.y, v23.x, v23.y);
            *(float4*)&Vs[r][c + 4] = make_float4(v45.x, v45.y, v67.x, v67.y);
        } else {
            float4 z = make_float4(0.f, 0.f, 0.f, 0.f);
            *(float4*)&Ks[r][c] = z; *(float4*)&Ks[r][c + 4] = z;
            *(float4*)&Vs[r][c] = z; *(float4*)&Vs[r][c + 4] = z;
        }
    }
    __syncthreads();

    int w = tid >> 5, lane = tid & 31;
    int sub = lane >> 3, di = lane & 7;
    int t = t0 + w * 4 + sub;
    int lo = max(t - 6, 0);
    int hi = min(t + 3, T_ - 1);
    int nw = hi - lo + 1;
    int rbase = lo - (t0 - 6);

    const __nv_bfloat16* qp = g_qb + ((size_t)(b * T_ + t)) * D_ + h * DH_ + di * 4;
    uint2 qa = *(const uint2*)qp;
    uint2 qbv = *(const uint2*)(qp + 32);
    float2 q01 = __bfloat1622float2(*(__nv_bfloat162*)&qa.x);
    float2 q23 = __bfloat1622float2(*(__nv_bfloat162*)&qa.y);
    float2 q45 = __bfloat1622float2(*(__nv_bfloat162*)&qbv.x);
    float2 q67 = __bfloat1622float2(*(__nv_bfloat162*)&qbv.y);

    float sc[10];
    float mx = -1e30f;
    #pragma unroll
    for (int jj = 0; jj < 10; jj++) {
        int r = rbase + jj;
        float4 k0 = *(const float4*)&Ks[r][di * 4];
        float4 k1 = *(const float4*)&Ks[r][32 + di * 4];
        float s = q01.x * k0.x + q01.y * k0.y + q23.x * k0.z + q23.y * k0.w
                + q45.x * k1.x + q45.y * k1.y + q67.x * k1.z + q67.y * k1.w;
        s += __shfl_xor_sync(0xFFFFFFFFu, s, 4);
        s += __shfl_xor_sync(0xFFFFFFFFu, s, 2);
        s += __shfl_xor_sync(0xFFFFFFFFu, s, 1);
        s = (jj < nw) ? s : -1e30f;
        sc[jj] = s;
        mx = fmaxf(mx, s);
    }

    float denom = 0.f;
    float a0 = 0.f, a1 = 0.f, a2 = 0.f, a3 = 0.f;
    float a4 = 0.f, a5 = 0.f, a6 = 0.f, a7 = 0.f;
    #pragma unroll
    for (int jj = 0; jj < 10; jj++) {
        float p = __expf(sc[jj] - mx);
        denom += p;
        int r = rbase + jj;
        float4 v0 = *(const float4*)&Vs[r][di * 4];
        float4 v1 = *(const float4*)&Vs[r][32 + di * 4];
        a0 = fmaf(p, v0.x, a0); a1 = fmaf(p, v0.y, a1);
        a2 = fmaf(p, v0.z, a2); a3 = fmaf(p, v0.w, a3);
        a4 = fmaf(p, v1.x, a4); a5 = fmaf(p, v1.y, a5);
        a6 = fmaf(p, v1.z, a6); a7 = fmaf(p, v1.w, a7);
    }
    float inv = 1.f / denom;

    __nv_bfloat162 o0 = __floats2bfloat162_rn(a0 * inv, a1 * inv);
    __nv_bfloat162 o1 = __floats2bfloat162_rn(a2 * inv, a3 * inv);
    __nv_bfloat162 o2 = __floats2bfloat162_rn(a4 * inv, a5 * inv);
    __nv_bfloat162 o3 = __floats2bfloat162_rn(a6 * inv, a7 * inv);
    __nv_bfloat16* cp = g_ctxb + ((size_t)(b * T_ + t)) * D_ + h * DH_ + di * 4;
    *(uint2*)cp        = make_uint2(*(uint32_t*)&o0, *(uint32_t*)&o1);
    *(uint2*)(cp + 32) = make_uint2(*(uint32_t*)&o2, *(uint32_t*)&o3);
}

// ---------------------------------------------------------------------------
// Launch
// ---------------------------------------------------------------------------
extern "C" void kernel_launch(void* const* d_in, const int* in_sizes, int n_in,
                              void* d_out, int out_size) {
    const float* x     = (const float*)d_in[0];
    const float* gamma = (const float*)d_in[1];
    const float* beta  = (const float*)d_in[2];
    const float* Wq    = (const float*)d_in[3];
    const float* bq    = (const float*)d_in[4];
    const float* Wk    = (const float*)d_in[5];
    const float* bk    = (const float*)d_in[6];
    const float* Wv    = (const float*)d_in[7];
    const float* bv    = (const float*)d_in[8];
    const float* Wo    = (const float*)d_in[9];
    const float* bo    = (const float*)d_in[10];
    float* out = (float*)d_out;

    pre_kernel<<<M_ + 2048, 128>>>(x, gamma, beta, Wq, Wk, Wv, Wo);
    qkv_kernel<<<dim3(D_/128, M_/128, 3), 256>>>(bq, bk, bv);
    attn_kernel<<<dim3(T_/TQ, B_*H_), 256>>>();
    out_kernel<<<dim3(D_/64, M_/64), 128>>>(bo, x, out);
}